// round 8
// baseline (speedup 1.0000x reference)
#include <cuda_runtime.h>
#include <cstdint>

// ---------------------------------------------------------------------------
// InteractionBlock (SchNet-style CFConv):
//   C     = cosine cutoff(||edge_weight||)                         [E]
//   W     = (ssp(edge_attr @ W1 + b1) @ W2 + b2) * C               [E,256]
//   msg   = W * (x @ lin1_w)[j]                                    [E,256]
//   agg   = segment_sum(msg, i)                                    [N,256]
//   out   = x + ssp(agg @ lin2_w + lin2_b)                         [N,256]
//
// edge_index dtype is ambiguous (JAX x64-disabled downcasts int64->int32),
// so a device-side probe detects the layout and a convert kernel produces
// clamped int32 index arrays. Everything else is fp32 with packed
// fma.rn.f32x2 (2x fp32 FMA rate on sm_103a).
// ---------------------------------------------------------------------------

#define TILE_E 64
#define FDIM 256
#define GDIM 50
#define GPAD 56          // padded K for edge_attr tile (multiple of 4, zero-filled)

#define NMAX 10240
#define EMAX 330000
__device__ float g_xs[NMAX * FDIM];
__device__ float g_agg[NMAX * FDIM];
__device__ int   g_si[EMAX];
__device__ int   g_sj[EMAX];
__device__ int   g_idx64;     // 1 = data is int64, 0 = int32

// ---- packed f32x2 helpers --------------------------------------------------
__device__ __forceinline__ unsigned long long pack2(float lo, float hi) {
    unsigned long long r;
    asm("mov.b64 %0, {%1, %2};" : "=l"(r) : "f"(lo), "f"(hi));
    return r;
}
__device__ __forceinline__ void unpack2(unsigned long long v, float& lo, float& hi) {
    asm("mov.b64 {%0, %1}, %2;" : "=f"(lo), "=f"(hi) : "l"(v));
}
__device__ __forceinline__ unsigned long long ffma2(unsigned long long a,
                                                    unsigned long long b,
                                                    unsigned long long c) {
    unsigned long long d;
    asm("fma.rn.f32x2 %0, %1, %2, %3;" : "=l"(d) : "l"(a), "l"(b), "l"(c));
    return d;
}

// shifted softplus: softplus(v) - log(2), numerically stable
__device__ __forceinline__ float sspf(float v) {
    return fmaxf(v, 0.f) + log1pf(expf(-fabsf(v))) - 0.69314718055994530942f;
}

// ---------------------------------------------------------------------------
// Index dtype probe: interpret the first 32 elements as int64; if ALL lie in
// [0, N) the data is int64 (int32 data would put a second random index in the
// hi word, failing w.p. 1 - 1e-4 per element). One warp, deterministic.
// ---------------------------------------------------------------------------
extern "C" __global__ void detect_idx_kernel(const long long* __restrict__ p,
                                             int count64, int N)
{
    int lane = threadIdx.x;                     // 32 threads
    int ok = 1;
    if (lane < count64) {
        long long v = p[lane];
        ok = (v >= 0 && v < (long long)N) ? 1 : 0;
    }
    unsigned all = __ballot_sync(0xFFFFFFFFu, ok);
    if (lane == 0) g_idx64 = (all == 0xFFFFFFFFu) ? 1 : 0;
}

extern "C" __global__ void convert_idx_kernel(const void* __restrict__ p,
                                              int E, int N)
{
    int e = blockIdx.x * blockDim.x + threadIdx.x;
    if (e >= E) return;
    int iv, jv;
    if (g_idx64) {
        const long long* q = (const long long*)p;
        iv = (int)q[e];
        jv = (int)q[E + e];
    } else {
        const int* q = (const int*)p;
        iv = q[e];
        jv = q[E + e];
    }
    // clamp defensively: any mis-detection degrades to wrong values, not a crash
    iv = min(max(iv, 0), N - 1);
    jv = min(max(jv, 0), N - 1);
    g_si[e] = iv;
    g_sj[e] = jv;
}

// ---------------------------------------------------------------------------
// Fused edge kernel. 256 threads, 64 edges per block.
// Thread t owns output column c = t for all 64 edges.
// K dimension packed into f32x2 lanes; accumulator pair summed at the end.
// ---------------------------------------------------------------------------
extern "C" __global__ void __launch_bounds__(256, 2)
edge_kernel(const float* __restrict__ ew,          // [E,3]
            const float* __restrict__ ea,          // [E,50]
            const float* __restrict__ w1,          // [50,256]
            const float* __restrict__ b1,          // [256]
            const float* __restrict__ w2,          // [256,256]
            const float* __restrict__ b2,          // [256]
            int E)
{
    extern __shared__ float sm[];
    float* ea_s = sm;                            // 64*56 floats
    float* hid  = sm + TILE_E * GPAD;            // 64*256 floats
    float* sC   = hid + TILE_E * FDIM;           // 64 floats
    int*   si   = (int*)(sC + TILE_E);           // 64 ints
    int*   sj   = si + TILE_E;                   // 64 ints

    const int tid = threadIdx.x;
    const int e0  = blockIdx.x * TILE_E;

    // --- indices + cutoff envelope ---
    if (tid < TILE_E) {
        int e = e0 + tid;
        float C = 0.f; int iv = 0, jv = 0;
        if (e < E) {
            iv = g_si[e];
            jv = g_sj[e];
            float a = ew[e*3+0], b = ew[e*3+1], c2 = ew[e*3+2];
            float d = sqrtf(a*a + b*b + c2*c2);
            if (d <= 2.0f)
                C = 0.5f * (cosf(d * 1.57079632679489662f) + 1.f);
        }
        si[tid] = iv; sj[tid] = jv; sC[tid] = C;
    }

    // --- load edge_attr tile [64,56], zero-padded ---
    for (int idx = tid; idx < TILE_E * GPAD; idx += 256) {
        int r = idx / GPAD, k = idx % GPAD;
        float v = 0.f;
        int e = e0 + r;
        if (k < GDIM && e < E) v = ea[e * GDIM + k];
        ea_s[idx] = v;
    }
    __syncthreads();

    const int c = tid;
    const float b1c = b1[c];

    // ---------------- Stage A: hid = ssp(ea @ W1 + b1) ----------------
    #pragma unroll 1
    for (int h = 0; h < 2; ++h) {
        unsigned long long acc[32];
        #pragma unroll
        for (int e = 0; e < 32; ++e) acc[e] = 0ULL;

        #pragma unroll 1
        for (int kc = 0; kc < 13; ++kc) {
            int k0 = kc * 4;
            float wv0 = (k0 + 0 < GDIM) ? w1[(k0+0)*FDIM + c] : 0.f;
            float wv1 = (k0 + 1 < GDIM) ? w1[(k0+1)*FDIM + c] : 0.f;
            float wv2 = (k0 + 2 < GDIM) ? w1[(k0+2)*FDIM + c] : 0.f;
            float wv3 = (k0 + 3 < GDIM) ? w1[(k0+3)*FDIM + c] : 0.f;
            unsigned long long wp0 = pack2(wv0, wv1);
            unsigned long long wp1 = pack2(wv2, wv3);
            const float* base = ea_s + (h*32) * GPAD + k0;
            #pragma unroll
            for (int e = 0; e < 32; ++e) {
                ulonglong2 v = *reinterpret_cast<const ulonglong2*>(base + e*GPAD);
                acc[e] = ffma2(v.x, wp0, acc[e]);
                acc[e] = ffma2(v.y, wp1, acc[e]);
            }
        }
        #pragma unroll
        for (int e = 0; e < 32; ++e) {
            float lo, hi; unpack2(acc[e], lo, hi);
            hid[(h*32 + e) * FDIM + c] = sspf(lo + hi + b1c);
        }
    }
    __syncthreads();

    // ---------------- Stage B: W = hid @ W2 + b2; epilogue ----------------
    const float b2c = b2[c];
    #pragma unroll 1
    for (int h = 0; h < 2; ++h) {
        unsigned long long acc[32];
        #pragma unroll
        for (int e = 0; e < 32; ++e) acc[e] = 0ULL;

        // software-prefetch w2 column values one k-chunk ahead (L2 hits)
        float wv0 = w2[0*FDIM + c], wv1 = w2[1*FDIM + c];
        float wv2 = w2[2*FDIM + c], wv3 = w2[3*FDIM + c];
        #pragma unroll 1
        for (int kc = 0; kc < 64; ++kc) {
            unsigned long long wp0 = pack2(wv0, wv1);
            unsigned long long wp1 = pack2(wv2, wv3);
            if (kc < 63) {
                int k0 = (kc + 1) * 4;
                wv0 = w2[(k0+0)*FDIM + c]; wv1 = w2[(k0+1)*FDIM + c];
                wv2 = w2[(k0+2)*FDIM + c]; wv3 = w2[(k0+3)*FDIM + c];
            }
            const float* base = hid + (h*32) * FDIM + kc * 4;
            #pragma unroll
            for (int e = 0; e < 32; ++e) {
                ulonglong2 v = *reinterpret_cast<const ulonglong2*>(base + e*FDIM);
                acc[e] = ffma2(v.x, wp0, acc[e]);
                acc[e] = ffma2(v.y, wp1, acc[e]);
            }
        }
        #pragma unroll
        for (int e = 0; e < 32; ++e) {
            int ee = h*32 + e;
            float lo, hi; unpack2(acc[e], lo, hi);
            float W = lo + hi + b2c;
            float msg = W * sC[ee] * g_xs[sj[ee] * FDIM + c];  // xs is L2-resident
            atomicAdd(&g_agg[si[ee] * FDIM + c], msg);          // agg is L2-resident
        }
    }
}

// ---------------------------------------------------------------------------
// Node GEMM. mode 0: g_xs = in @ w.  mode 1: out = xres + ssp(g_agg @ w + bias)
// 64 rows per block, thread t owns column t. Same f32x2 packing.
// ---------------------------------------------------------------------------
extern "C" __global__ void __launch_bounds__(256, 2)
node_gemm(const float* __restrict__ in,     // mode0: x    mode1: ignored (g_agg)
          const float* __restrict__ w,
          const float* __restrict__ bias,   // mode1 only
          const float* __restrict__ xres,   // mode1 only
          float* __restrict__ out,          // mode1 only (mode0 -> g_xs)
          int N, int mode)
{
    extern __shared__ float tile[];          // 64*256 floats
    const int tid = threadIdx.x;
    const int n0  = blockIdx.x * 64;

    const float* src = (mode == 0) ? in : (const float*)g_agg;
    float* dst       = (mode == 0) ? g_xs : out;

    for (int idx = tid; idx < 64 * FDIM; idx += 256) {
        int r = idx >> 8;
        float v = 0.f;
        if (n0 + r < N) v = src[(n0 + r) * FDIM + (idx & 255)];
        tile[idx] = v;
    }
    __syncthreads();

    const int c = tid;
    #pragma unroll 1
    for (int h = 0; h < 2; ++h) {
        unsigned long long acc[32];
        #pragma unroll
        for (int r = 0; r < 32; ++r) acc[r] = 0ULL;

        float wv0 = w[0*FDIM + c], wv1 = w[1*FDIM + c];
        float wv2 = w[2*FDIM + c], wv3 = w[3*FDIM + c];
        #pragma unroll 1
        for (int kc = 0; kc < 64; ++kc) {
            unsigned long long wp0 = pack2(wv0, wv1);
            unsigned long long wp1 = pack2(wv2, wv3);
            if (kc < 63) {
                int k0 = (kc + 1) * 4;
                wv0 = w[(k0+0)*FDIM + c]; wv1 = w[(k0+1)*FDIM + c];
                wv2 = w[(k0+2)*FDIM + c]; wv3 = w[(k0+3)*FDIM + c];
            }
            const float* base = tile + (h*32) * FDIM + kc * 4;
            #pragma unroll
            for (int r = 0; r < 32; ++r) {
                ulonglong2 v = *reinterpret_cast<const ulonglong2*>(base + r*FDIM);
                acc[r] = ffma2(v.x, wp0, acc[r]);
                acc[r] = ffma2(v.y, wp1, acc[r]);
            }
        }
        #pragma unroll
        for (int r = 0; r < 32; ++r) {
            int n = n0 + h*32 + r;
            if (n < N) {
                float lo, hi; unpack2(acc[r], lo, hi);
                float val = lo + hi;
                if (mode == 0) {
                    dst[n * FDIM + c] = val;
                } else {
                    dst[n * FDIM + c] = xres[n * FDIM + c] + sspf(val + bias[c]);
                }
            }
        }
    }
}

extern "C" __global__ void zero_agg_kernel(int total4) {
    int i = blockIdx.x * blockDim.x + threadIdx.x;
    if (i < total4) {
        float4 z; z.x = 0.f; z.y = 0.f; z.z = 0.f; z.w = 0.f;
        reinterpret_cast<float4*>(g_agg)[i] = z;
    }
}

// ---------------------------------------------------------------------------

static const int SMEM_EDGE = (TILE_E * GPAD + TILE_E * FDIM + TILE_E) * 4 + TILE_E * 2 * 4;
static const int SMEM_NODE = 64 * FDIM * 4;

extern "C" void kernel_launch(void* const* d_in, const int* in_sizes, int n_in,
                              void* d_out, int out_size)
{
    const float* x    = (const float*)d_in[0];
    const void*  eidx = d_in[1];
    const float* ew   = (const float*)d_in[2];
    const float* ea   = (const float*)d_in[3];
    const float* w1   = (const float*)d_in[4];
    const float* b1   = (const float*)d_in[5];
    const float* w2   = (const float*)d_in[6];
    const float* b2   = (const float*)d_in[7];
    const float* l1   = (const float*)d_in[8];
    const float* l2   = (const float*)d_in[9];
    const float* l2b  = (const float*)d_in[10];

    const int N = in_sizes[0] / FDIM;     // x is [N,256]
    const int E = in_sizes[1] / 2;        // edge_index is [2,E]

    cudaFuncSetAttribute(edge_kernel, cudaFuncAttributeMaxDynamicSharedMemorySize, SMEM_EDGE);
    cudaFuncSetAttribute(node_gemm,   cudaFuncAttributeMaxDynamicSharedMemorySize, SMEM_NODE);

    // dtype probe + index conversion (handles int64 or int32 edge_index)
    // count64: how many int64 slots can safely be read = (total elements)/2
    // if data is int64, total elements = 2E (all readable); if int32, E slots.
    // E/1 >= 32 always here; use min(32, E/2) to be safe for tiny E.
    int count64 = E / 2 < 32 ? E / 2 : 32;
    detect_idx_kernel<<<1, 32>>>((const long long*)eidx, count64, N);
    convert_idx_kernel<<<(E + 255) / 256, 256>>>(eidx, E, N);

    const int total4 = (N * FDIM) / 4;
    zero_agg_kernel<<<(total4 + 255) / 256, 256>>>(total4);

    // xs = x @ lin1_w  -> g_xs
    node_gemm<<<(N + 63) / 64, 256, SMEM_NODE>>>(x, l1, nullptr, nullptr, nullptr, N, 0);

    // fused edge MLP + cutoff + gather + scatter-add
    edge_kernel<<<(E + TILE_E - 1) / TILE_E, 256, SMEM_EDGE>>>(ew, ea, w1, b1, w2, b2, E);

    // out = x + ssp(agg @ lin2_w + lin2_b)
    node_gemm<<<(N + 63) / 64, 256, SMEM_NODE>>>(nullptr, l2, l2b, x, (float*)d_out, N, 1);
}

// round 9
// speedup vs baseline: 1.0199x; 1.0199x over previous
#include <cuda_runtime.h>
#include <cstdint>

// ---------------------------------------------------------------------------
// InteractionBlock (SchNet-style CFConv), fp32 with packed fma.rn.f32x2.
//   W   = (ssp(edge_attr @ W1 + b1) @ W2 + b2) * cutoff(d)     [E,256]
//   msg = W * (x @ lin1_w)[j];  agg = segment_sum(msg, i)
//   out = x + ssp(agg @ lin2_w + lin2_b)
//
// R9: occupancy-oriented restructure. Edge tile 48, processed in 3 chunks of
// 16 edges (32 acc regs) -> 3 blocks/SM (24 warps) instead of 2 blocks with
// 64 acc regs. Distance-2 weight prefetch in both MLP stages. Node GEMM
// re-tiled to 32 rows (grid 313, ~2 blocks/SM).
// ---------------------------------------------------------------------------

#define TILE_E 48
#define ECH    16            // edges per accumulation chunk
#define NCHE   3             // chunks per edge tile
#define FDIM   256
#define GDIM   50
#define GPAD   56            // padded K for edge_attr tile

#define NMAX 10240
#define EMAX 330000
__device__ float g_xs[NMAX * FDIM];
__device__ float g_agg[NMAX * FDIM];
__device__ int   g_si[EMAX];
__device__ int   g_sj[EMAX];
__device__ int   g_idx64;

// ---- packed f32x2 helpers --------------------------------------------------
__device__ __forceinline__ unsigned long long pack2(float lo, float hi) {
    unsigned long long r;
    asm("mov.b64 %0, {%1, %2};" : "=l"(r) : "f"(lo), "f"(hi));
    return r;
}
__device__ __forceinline__ void unpack2(unsigned long long v, float& lo, float& hi) {
    asm("mov.b64 {%0, %1}, %2;" : "=f"(lo), "=f"(hi) : "l"(v));
}
__device__ __forceinline__ unsigned long long ffma2(unsigned long long a,
                                                    unsigned long long b,
                                                    unsigned long long c) {
    unsigned long long d;
    asm("fma.rn.f32x2 %0, %1, %2, %3;" : "=l"(d) : "l"(a), "l"(b), "l"(c));
    return d;
}

__device__ __forceinline__ float sspf(float v) {
    return fmaxf(v, 0.f) + log1pf(expf(-fabsf(v))) - 0.69314718055994530942f;
}

// ---------------------------------------------------------------------------
// edge_index dtype probe (JAX x64-disabled may hand us int32 despite int64
// in the reference). One warp, deterministic.
// ---------------------------------------------------------------------------
extern "C" __global__ void detect_idx_kernel(const long long* __restrict__ p,
                                             int count64, int N)
{
    int lane = threadIdx.x;
    int ok = 1;
    if (lane < count64) {
        long long v = p[lane];
        ok = (v >= 0 && v < (long long)N) ? 1 : 0;
    }
    unsigned all = __ballot_sync(0xFFFFFFFFu, ok);
    if (lane == 0) g_idx64 = (all == 0xFFFFFFFFu) ? 1 : 0;
}

extern "C" __global__ void convert_idx_kernel(const void* __restrict__ p,
                                              int E, int N)
{
    int e = blockIdx.x * blockDim.x + threadIdx.x;
    if (e >= E) return;
    int iv, jv;
    if (g_idx64) {
        const long long* q = (const long long*)p;
        iv = (int)q[e];
        jv = (int)q[E + e];
    } else {
        const int* q = (const int*)p;
        iv = q[e];
        jv = q[E + e];
    }
    iv = min(max(iv, 0), N - 1);
    jv = min(max(jv, 0), N - 1);
    g_si[e] = iv;
    g_sj[e] = jv;
}

// ---------------------------------------------------------------------------
// Fused edge kernel. 256 threads, 48 edges/block, 3 chunks of 16 edges.
// Thread t owns output column c = t. K packed in f32x2 lanes.
// ---------------------------------------------------------------------------
extern "C" __global__ void __launch_bounds__(256, 3)
edge_kernel(const float* __restrict__ ew,          // [E,3]
            const float* __restrict__ ea,          // [E,50]
            const float* __restrict__ w1,          // [50,256]
            const float* __restrict__ b1,          // [256]
            const float* __restrict__ w2,          // [256,256]
            const float* __restrict__ b2,          // [256]
            int E)
{
    extern __shared__ float sm[];
    float* ea_s = sm;                              // 48*56
    float* hid  = sm + TILE_E * GPAD;              // 48*256
    float* sC   = hid + TILE_E * FDIM;             // 48
    int*   si   = (int*)(sC + TILE_E);             // 48
    int*   sj   = si + TILE_E;                     // 48

    const int tid = threadIdx.x;
    const int e0  = blockIdx.x * TILE_E;

    if (tid < TILE_E) {
        int e = e0 + tid;
        float C = 0.f; int iv = 0, jv = 0;
        if (e < E) {
            iv = g_si[e];
            jv = g_sj[e];
            float a = ew[e*3+0], b = ew[e*3+1], c2 = ew[e*3+2];
            float d = sqrtf(a*a + b*b + c2*c2);
            if (d <= 2.0f)
                C = 0.5f * (cosf(d * 1.57079632679489662f) + 1.f);
        }
        si[tid] = iv; sj[tid] = jv; sC[tid] = C;
    }

    for (int idx = tid; idx < TILE_E * GPAD; idx += 256) {
        int r = idx / GPAD, k = idx % GPAD;
        float v = 0.f;
        int e = e0 + r;
        if (k < GDIM && e < E) v = ea[e * GDIM + k];
        ea_s[idx] = v;
    }
    __syncthreads();

    const int c = tid;
    const float b1c = b1[c];

    // ---------------- Stage A: hid = ssp(ea @ W1 + b1), 13 k-chunks --------
    #pragma unroll 1
    for (int ch = 0; ch < NCHE; ++ch) {
        unsigned long long acc[ECH];
        #pragma unroll
        for (int e = 0; e < ECH; ++e) acc[e] = 0ULL;

        // distance-2 rotating prefetch of w1 (guarded: k >= 50 -> 0)
        float a0 = w1[0*FDIM + c], a1 = w1[1*FDIM + c];
        float a2 = w1[2*FDIM + c], a3 = w1[3*FDIM + c];
        float p0 = w1[4*FDIM + c], p1 = w1[5*FDIM + c];
        float p2 = w1[6*FDIM + c], p3 = w1[7*FDIM + c];
        #pragma unroll 1
        for (int kc = 0; kc < 13; ++kc) {
            unsigned long long wp0 = pack2(a0, a1);
            unsigned long long wp1 = pack2(a2, a3);
            a0 = p0; a1 = p1; a2 = p2; a3 = p3;
            if (kc + 2 < 13) {
                int k0 = (kc + 2) * 4;
                p0 = (k0 + 0 < GDIM) ? w1[(k0+0)*FDIM + c] : 0.f;
                p1 = (k0 + 1 < GDIM) ? w1[(k0+1)*FDIM + c] : 0.f;
                p2 = (k0 + 2 < GDIM) ? w1[(k0+2)*FDIM + c] : 0.f;
                p3 = (k0 + 3 < GDIM) ? w1[(k0+3)*FDIM + c] : 0.f;
            }
            const float* base = ea_s + (ch * ECH) * GPAD + kc * 4;
            #pragma unroll
            for (int e = 0; e < ECH; ++e) {
                ulonglong2 v = *reinterpret_cast<const ulonglong2*>(base + e*GPAD);
                acc[e] = ffma2(v.x, wp0, acc[e]);
                acc[e] = ffma2(v.y, wp1, acc[e]);
            }
        }
        #pragma unroll
        for (int e = 0; e < ECH; ++e) {
            float lo, hi; unpack2(acc[e], lo, hi);
            hid[(ch * ECH + e) * FDIM + c] = sspf(lo + hi + b1c);
        }
    }
    __syncthreads();

    // ---------------- Stage B: W = hid @ W2 + b2; epilogue -----------------
    const float b2c = b2[c];
    #pragma unroll 1
    for (int ch = 0; ch < NCHE; ++ch) {
        unsigned long long acc[ECH];
        #pragma unroll
        for (int e = 0; e < ECH; ++e) acc[e] = 0ULL;

        // distance-2 rotating prefetch of w2 column values
        float a0 = w2[0*FDIM + c], a1 = w2[1*FDIM + c];
        float a2 = w2[2*FDIM + c], a3 = w2[3*FDIM + c];
        float p0 = w2[4*FDIM + c], p1 = w2[5*FDIM + c];
        float p2 = w2[6*FDIM + c], p3 = w2[7*FDIM + c];
        #pragma unroll 1
        for (int kc = 0; kc < 64; ++kc) {
            unsigned long long wp0 = pack2(a0, a1);
            unsigned long long wp1 = pack2(a2, a3);
            a0 = p0; a1 = p1; a2 = p2; a3 = p3;
            if (kc + 2 < 64) {
                int k0 = (kc + 2) * 4;
                p0 = w2[(k0+0)*FDIM + c]; p1 = w2[(k0+1)*FDIM + c];
                p2 = w2[(k0+2)*FDIM + c]; p3 = w2[(k0+3)*FDIM + c];
            }
            const float* base = hid + (ch * ECH) * FDIM + kc * 4;
            #pragma unroll
            for (int e = 0; e < ECH; ++e) {
                ulonglong2 v = *reinterpret_cast<const ulonglong2*>(base + e*FDIM);
                acc[e] = ffma2(v.x, wp0, acc[e]);
                acc[e] = ffma2(v.y, wp1, acc[e]);
            }
        }
        #pragma unroll
        for (int e = 0; e < ECH; ++e) {
            int ee = ch * ECH + e;
            float lo, hi; unpack2(acc[e], lo, hi);
            float W = lo + hi + b2c;
            float msg = W * sC[ee] * g_xs[sj[ee] * FDIM + c];   // L2-resident gather
            atomicAdd(&g_agg[si[ee] * FDIM + c], msg);           // L2-resident RED
        }
    }
}

// ---------------------------------------------------------------------------
// Node GEMM. mode 0: g_xs = in @ w.  mode 1: out = xres + ssp(g_agg @ w + b).
// 32 rows/block (grid ~313 -> ~2 blocks/SM), 2 chunks of 16 rows.
// ---------------------------------------------------------------------------
extern "C" __global__ void __launch_bounds__(256, 3)
node_gemm(const float* __restrict__ in,
          const float* __restrict__ w,
          const float* __restrict__ bias,
          const float* __restrict__ xres,
          float* __restrict__ out,
          int N, int mode)
{
    extern __shared__ float tile[];          // 32*256 floats
    const int tid = threadIdx.x;
    const int n0  = blockIdx.x * 32;

    const float* src = (mode == 0) ? in : (const float*)g_agg;
    float* dst       = (mode == 0) ? g_xs : out;

    // vectorized tile load: 32 rows x 64 float4 = 2048 float4, 8 per thread
    {
        const float4* s4 = reinterpret_cast<const float4*>(src);
        float4* t4 = reinterpret_cast<float4*>(tile);
        #pragma unroll
        for (int q = 0; q < 8; ++q) {
            int idx = q * 256 + tid;         // [0, 2048)
            int r = idx >> 6;                // /64
            float4 v = make_float4(0.f, 0.f, 0.f, 0.f);
            if (n0 + r < N) v = s4[(size_t)(n0 + r) * 64 + (idx & 63)];
            t4[idx] = v;
        }
    }
    __syncthreads();

    const int c = tid;
    #pragma unroll 1
    for (int ch = 0; ch < 2; ++ch) {
        unsigned long long acc[16];
        #pragma unroll
        for (int r = 0; r < 16; ++r) acc[r] = 0ULL;

        float a0 = w[0*FDIM + c], a1 = w[1*FDIM + c];
        float a2 = w[2*FDIM + c], a3 = w[3*FDIM + c];
        float p0 = w[4*FDIM + c], p1 = w[5*FDIM + c];
        float p2 = w[6*FDIM + c], p3 = w[7*FDIM + c];
        #pragma unroll 1
        for (int kc = 0; kc < 64; ++kc) {
            unsigned long long wp0 = pack2(a0, a1);
            unsigned long long wp1 = pack2(a2, a3);
            a0 = p0; a1 = p1; a2 = p2; a3 = p3;
            if (kc + 2 < 64) {
                int k0 = (kc + 2) * 4;
                p0 = w[(k0+0)*FDIM + c]; p1 = w[(k0+1)*FDIM + c];
                p2 = w[(k0+2)*FDIM + c]; p3 = w[(k0+3)*FDIM + c];
            }
            const float* base = tile + (ch * 16) * FDIM + kc * 4;
            #pragma unroll
            for (int r = 0; r < 16; ++r) {
                ulonglong2 v = *reinterpret_cast<const ulonglong2*>(base + r*FDIM);
                acc[r] = ffma2(v.x, wp0, acc[r]);
                acc[r] = ffma2(v.y, wp1, acc[r]);
            }
        }
        #pragma unroll
        for (int r = 0; r < 16; ++r) {
            int n = n0 + ch * 16 + r;
            if (n < N) {
                float lo, hi; unpack2(acc[r], lo, hi);
                float val = lo + hi;
                if (mode == 0) {
                    dst[n * FDIM + c] = val;
                } else {
                    dst[n * FDIM + c] = xres[n * FDIM + c] + sspf(val + bias[c]);
                }
            }
        }
    }
}

extern "C" __global__ void zero_agg_kernel(int total4) {
    int i = blockIdx.x * blockDim.x + threadIdx.x;
    if (i < total4) {
        float4 z; z.x = 0.f; z.y = 0.f; z.z = 0.f; z.w = 0.f;
        reinterpret_cast<float4*>(g_agg)[i] = z;
    }
}

// ---------------------------------------------------------------------------

static const int SMEM_EDGE = (TILE_E * GPAD + TILE_E * FDIM + TILE_E) * 4 + TILE_E * 2 * 4;
static const int SMEM_NODE = 32 * FDIM * 4;

extern "C" void kernel_launch(void* const* d_in, const int* in_sizes, int n_in,
                              void* d_out, int out_size)
{
    const float* x    = (const float*)d_in[0];
    const void*  eidx = d_in[1];
    const float* ew   = (const float*)d_in[2];
    const float* ea   = (const float*)d_in[3];
    const float* w1   = (const float*)d_in[4];
    const float* b1   = (const float*)d_in[5];
    const float* w2   = (const float*)d_in[6];
    const float* b2   = (const float*)d_in[7];
    const float* l1   = (const float*)d_in[8];
    const float* l2   = (const float*)d_in[9];
    const float* l2b  = (const float*)d_in[10];

    const int N = in_sizes[0] / FDIM;     // x is [N,256]
    const int E = in_sizes[1] / 2;        // edge_index is [2,E]

    cudaFuncSetAttribute(edge_kernel, cudaFuncAttributeMaxDynamicSharedMemorySize, SMEM_EDGE);
    cudaFuncSetAttribute(node_gemm,   cudaFuncAttributeMaxDynamicSharedMemorySize, SMEM_NODE);

    int count64 = E / 2 < 32 ? E / 2 : 32;
    detect_idx_kernel<<<1, 32>>>((const long long*)eidx, count64, N);
    convert_idx_kernel<<<(E + 255) / 256, 256>>>(eidx, E, N);

    const int total4 = (N * FDIM) / 4;
    zero_agg_kernel<<<(total4 + 255) / 256, 256>>>(total4);

    // xs = x @ lin1_w  -> g_xs
    node_gemm<<<(N + 31) / 32, 256, SMEM_NODE>>>(x, l1, nullptr, nullptr, nullptr, N, 0);

    // fused edge MLP + cutoff + gather + scatter-add
    edge_kernel<<<(E + TILE_E - 1) / TILE_E, 256, SMEM_EDGE>>>(ew, ea, w1, b1, w2, b2, E);

    // out = x + ssp(agg @ lin2_w + lin2_b)
    node_gemm<<<(N + 31) / 32, 256, SMEM_NODE>>>(nullptr, l2, l2b, x, (float*)d_out, N, 1);
}

// round 10
// speedup vs baseline: 1.0666x; 1.0458x over previous
#include <cuda_runtime.h>
#include <cstdint>

// ---------------------------------------------------------------------------
// InteractionBlock (SchNet CFConv), fp32, packed fma.rn.f32x2.
// R10: stage B of the edge kernel rewritten as a smem-tiled outer-product
// SGEMM: TILE_E=32, thread tile 8 edges x 4 cols, w2 double-buffered through
// shared memory (one pass over w2 per block). Warm kernel aligns ncu capture
// onto the edge kernel.
// ---------------------------------------------------------------------------

#define TILE_E 32
#define FDIM   256
#define GDIM   50
#define GPAD   56

#define NMAX 10240
#define EMAX 330000
__device__ float g_xs[NMAX * FDIM];
__device__ float g_agg[NMAX * FDIM];
__device__ int   g_si[EMAX];
__device__ int   g_sj[EMAX];
__device__ int   g_idx64;

typedef unsigned long long u64;

// ---- packed f32x2 helpers --------------------------------------------------
__device__ __forceinline__ u64 pack2(float lo, float hi) {
    u64 r;
    asm("mov.b64 %0, {%1, %2};" : "=l"(r) : "f"(lo), "f"(hi));
    return r;
}
__device__ __forceinline__ void unpack2(u64 v, float& lo, float& hi) {
    asm("mov.b64 {%0, %1}, %2;" : "=f"(lo), "=f"(hi) : "l"(v));
}
__device__ __forceinline__ u64 ffma2(u64 a, u64 b, u64 c) {
    u64 d;
    asm("fma.rn.f32x2 %0, %1, %2, %3;" : "=l"(d) : "l"(a), "l"(b), "l"(c));
    return d;
}

__device__ __forceinline__ float sspf(float v) {
    return fmaxf(v, 0.f) + log1pf(expf(-fabsf(v))) - 0.69314718055994530942f;
}

// ---------------------------------------------------------------------------
// edge_index dtype probe + convert (int64 vs int32 ambiguity)
// ---------------------------------------------------------------------------
extern "C" __global__ void detect_idx_kernel(const long long* __restrict__ p,
                                             int count64, int N)
{
    int lane = threadIdx.x;
    int ok = 1;
    if (lane < count64) {
        long long v = p[lane];
        ok = (v >= 0 && v < (long long)N) ? 1 : 0;
    }
    unsigned all = __ballot_sync(0xFFFFFFFFu, ok);
    if (lane == 0) g_idx64 = (all == 0xFFFFFFFFu) ? 1 : 0;
}

extern "C" __global__ void convert_idx_kernel(const void* __restrict__ p,
                                              int E, int N)
{
    int e = blockIdx.x * blockDim.x + threadIdx.x;
    if (e >= E) return;
    int iv, jv;
    if (g_idx64) {
        const long long* q = (const long long*)p;
        iv = (int)q[e];
        jv = (int)q[E + e];
    } else {
        const int* q = (const int*)p;
        iv = q[e];
        jv = q[E + e];
    }
    iv = min(max(iv, 0), N - 1);
    jv = min(max(jv, 0), N - 1);
    g_si[e] = iv;
    g_sj[e] = jv;
}

// L2 warmer for w2 (also shifts the edge kernel to ncu launch index 5)
extern "C" __global__ void warm_kernel(const float* __restrict__ w2) {
    int i = blockIdx.x * blockDim.x + threadIdx.x;   // 65536 threads
    float v = w2[i];
    if (v == 123456789.0f) g_agg[0] += 1.0f;         // never taken; defeats DCE
}

// ---------------------------------------------------------------------------
// Fused edge kernel. 256 threads, 32 edges per block.
// Stage A: hid = ssp(ea @ W1 + b1)   (col-per-thread, 2 chunks of 16 edges)
// Stage B: W = hid @ W2 + b2         (outer-product 8e x 4c, smem-slabbed w2)
// Epilogue: msg = W*C*xs[j], atomicAdd into agg[i].
// ---------------------------------------------------------------------------

// smem layout (floats)
#define HID_OFF   0                      // 32*256 = 8192 floats
#define UNION_OFF 8192                   // ea_s (1792 f) / pbuf (4096 f) union
#define SC_OFF    (8192 + 4096)          // 32 floats
#define SI_OFF    (SC_OFF + 32)
#define SJ_OFF    (SI_OFF + 32)
#define SMEM_EDGE_FLOATS (SJ_OFF + 32)

extern "C" __global__ void __launch_bounds__(256, 2)
edge_kernel(const float* __restrict__ ew,          // [E,3]
            const float* __restrict__ ea,          // [E,50]
            const float* __restrict__ w1,          // [50,256]
            const float* __restrict__ b1,          // [256]
            const float* __restrict__ w2,          // [256,256]
            const float* __restrict__ b2,          // [256]
            int E)
{
    extern __shared__ float sm[];
    float* hid  = sm + HID_OFF;
    float* ea_s = sm + UNION_OFF;
    float* sC   = sm + SC_OFF;
    int*   si   = (int*)(sm + SI_OFF);
    int*   sj   = (int*)(sm + SJ_OFF);

    const int tid = threadIdx.x;
    const int e0  = blockIdx.x * TILE_E;

    if (tid < TILE_E) {
        int e = e0 + tid;
        float C = 0.f; int iv = 0, jv = 0;
        if (e < E) {
            iv = g_si[e];
            jv = g_sj[e];
            float a = ew[e*3+0], b = ew[e*3+1], c2 = ew[e*3+2];
            float d = sqrtf(a*a + b*b + c2*c2);
            if (d <= 2.0f)
                C = 0.5f * (cosf(d * 1.57079632679489662f) + 1.f);
        }
        si[tid] = iv; sj[tid] = jv; sC[tid] = C;
    }

    // edge_attr tile [32,56], zero-padded
    for (int idx = tid; idx < TILE_E * GPAD; idx += 256) {
        int r = idx / GPAD, k = idx % GPAD;
        float v = 0.f;
        int e = e0 + r;
        if (k < GDIM && e < E) v = ea[e * GDIM + k];
        ea_s[idx] = v;
    }
    __syncthreads();

    // ---------------- Stage A: hid = ssp(ea @ W1 + b1) ---------------------
    {
        const int c = tid;
        const float b1c = b1[c];
        #pragma unroll 1
        for (int ch = 0; ch < 2; ++ch) {
            u64 acc[16];
            #pragma unroll
            for (int e = 0; e < 16; ++e) acc[e] = 0ULL;

            float a0 = w1[0*FDIM + c], a1 = w1[1*FDIM + c];
            float a2 = w1[2*FDIM + c], a3 = w1[3*FDIM + c];
            float p0 = w1[4*FDIM + c], p1 = w1[5*FDIM + c];
            float p2 = w1[6*FDIM + c], p3 = w1[7*FDIM + c];
            #pragma unroll 1
            for (int kc = 0; kc < 13; ++kc) {
                u64 wp0 = pack2(a0, a1);
                u64 wp1 = pack2(a2, a3);
                a0 = p0; a1 = p1; a2 = p2; a3 = p3;
                if (kc + 2 < 13) {
                    int k0 = (kc + 2) * 4;
                    p0 = (k0 + 0 < GDIM) ? w1[(k0+0)*FDIM + c] : 0.f;
                    p1 = (k0 + 1 < GDIM) ? w1[(k0+1)*FDIM + c] : 0.f;
                    p2 = (k0 + 2 < GDIM) ? w1[(k0+2)*FDIM + c] : 0.f;
                    p3 = (k0 + 3 < GDIM) ? w1[(k0+3)*FDIM + c] : 0.f;
                }
                const float* base = ea_s + (ch * 16) * GPAD + kc * 4;
                #pragma unroll
                for (int e = 0; e < 16; ++e) {
                    ulonglong2 v = *reinterpret_cast<const ulonglong2*>(base + e*GPAD);
                    acc[e] = ffma2(v.x, wp0, acc[e]);
                    acc[e] = ffma2(v.y, wp1, acc[e]);
                }
            }
            #pragma unroll
            for (int e = 0; e < 16; ++e) {
                float lo, hi; unpack2(acc[e], lo, hi);
                hid[(ch * 16 + e) * FDIM + c] = sspf(lo + hi + b1c);
            }
        }
    }
    __syncthreads();   // hid complete; ea_s region now free for pbuf

    // ---------------- Stage B: outer-product SGEMM -------------------------
    // thread tile: edges ty*8..ty*8+7, cols tx + 64*u (u=0..3)
    const int tx = tid & 63;
    const int ty = tid >> 6;

    u64* pbuf = (u64*)(sm + UNION_OFF);      // [2][4*256] u64, 8KB per buffer

    float ra[4], rb[4];
    // prologue: slab 0 -> pbuf[0]; slab 1 -> regs
    {
        int k0 = 2 * ty;                      // this thread's k-pair row in slab
        #pragma unroll
        for (int m = 0; m < 4; ++m) {
            int cc = tx + 64 * m;
            ra[m] = w2[(k0    ) * FDIM + cc];
            rb[m] = w2[(k0 + 1) * FDIM + cc];
        }
        #pragma unroll
        for (int m = 0; m < 4; ++m)
            pbuf[ty * 256 + tx + 64 * m] = pack2(ra[m], rb[m]);
        #pragma unroll
        for (int m = 0; m < 4; ++m) {
            int cc = tx + 64 * m;
            ra[m] = w2[(8 + k0    ) * FDIM + cc];
            rb[m] = w2[(8 + k0 + 1) * FDIM + cc];
        }
    }

    u64 acc[8][4];
    #pragma unroll
    for (int e = 0; e < 8; ++e)
        #pragma unroll
        for (int u = 0; u < 4; ++u) acc[e][u] = 0ULL;

    #pragma unroll 1
    for (int s = 0; s < 32; ++s) {
        __syncthreads();                      // pbuf[s&1] ready; (s+1)&1 free
        u64* curp = pbuf + (s & 1) * 1024;
        if (s + 1 < 32) {
            u64* nxt = pbuf + ((s + 1) & 1) * 1024;
            #pragma unroll
            for (int m = 0; m < 4; ++m)
                nxt[ty * 256 + tx + 64 * m] = pack2(ra[m], rb[m]);
        }
        if (s + 2 < 32) {
            int k0 = (s + 2) * 8 + 2 * ty;
            #pragma unroll
            for (int m = 0; m < 4; ++m) {
                int cc = tx + 64 * m;
                ra[m] = w2[(k0    ) * FDIM + cc];
                rb[m] = w2[(k0 + 1) * FDIM + cc];
            }
        }
        // compute: 4 k-pairs of this slab
        #pragma unroll
        for (int kp = 0; kp < 4; ++kp) {
            u64 bfr[4];
            #pragma unroll
            for (int u = 0; u < 4; ++u)
                bfr[u] = curp[kp * 256 + tx + 64 * u];
            #pragma unroll
            for (int e = 0; e < 8; ++e) {
                u64 a = *reinterpret_cast<const u64*>(
                    hid + (ty * 8 + e) * FDIM + s * 8 + kp * 2);
                #pragma unroll
                for (int u = 0; u < 4; ++u)
                    acc[e][u] = ffma2(a, bfr[u], acc[e][u]);
            }
        }
    }

    // ---------------- epilogue: cutoff * gather * scatter-add --------------
    float b2v[4];
    #pragma unroll
    for (int u = 0; u < 4; ++u) b2v[u] = b2[tx + 64 * u];

    #pragma unroll
    for (int e = 0; e < 8; ++e) {
        int ee = ty * 8 + e;
        int jj = sj[ee], ii = si[ee];
        float Ce = sC[ee];
        const float* xr = g_xs + (size_t)jj * FDIM;
        float*       ar = g_agg + (size_t)ii * FDIM;
        #pragma unroll
        for (int u = 0; u < 4; ++u) {
            float lo, hi; unpack2(acc[e][u], lo, hi);
            float W = lo + hi + b2v[u];
            int cc = tx + 64 * u;
            atomicAdd(&ar[cc], W * Ce * xr[cc]);
        }
    }
}

// ---------------------------------------------------------------------------
// Node GEMM (unchanged from R9). mode 0: g_xs = in @ w.
// mode 1: out = xres + ssp(g_agg @ w + bias). 32 rows/block.
// ---------------------------------------------------------------------------
extern "C" __global__ void __launch_bounds__(256, 3)
node_gemm(const float* __restrict__ in,
          const float* __restrict__ w,
          const float* __restrict__ bias,
          const float* __restrict__ xres,
          float* __restrict__ out,
          int N, int mode)
{
    extern __shared__ float tile[];          // 32*256 floats
    const int tid = threadIdx.x;
    const int n0  = blockIdx.x * 32;

    const float* src = (mode == 0) ? in : (const float*)g_agg;
    float* dst       = (mode == 0) ? g_xs : out;

    {
        const float4* s4 = reinterpret_cast<const float4*>(src);
        float4* t4 = reinterpret_cast<float4*>(tile);
        #pragma unroll
        for (int q = 0; q < 8; ++q) {
            int idx = q * 256 + tid;
            int r = idx >> 6;
            float4 v = make_float4(0.f, 0.f, 0.f, 0.f);
            if (n0 + r < N) v = s4[(size_t)(n0 + r) * 64 + (idx & 63)];
            t4[idx] = v;
        }
    }
    __syncthreads();

    const int c = tid;
    #pragma unroll 1
    for (int ch = 0; ch < 2; ++ch) {
        u64 acc[16];
        #pragma unroll
        for (int r = 0; r < 16; ++r) acc[r] = 0ULL;

        float a0 = w[0*FDIM + c], a1 = w[1*FDIM + c];
        float a2 = w[2*FDIM + c], a3 = w[3*FDIM + c];
        float p0 = w[4*FDIM + c], p1 = w[5*FDIM + c];
        float p2 = w[6*FDIM + c], p3 = w[7*FDIM + c];
        #pragma unroll 1
        for (int kc = 0; kc < 64; ++kc) {
            u64 wp0 = pack2(a0, a1);
            u64 wp1 = pack2(a2, a3);
            a0 = p0; a1 = p1; a2 = p2; a3 = p3;
            if (kc + 2 < 64) {
                int k0 = (kc + 2) * 4;
                p0 = w[(k0+0)*FDIM + c]; p1 = w[(k0+1)*FDIM + c];
                p2 = w[(k0+2)*FDIM + c]; p3 = w[(k0+3)*FDIM + c];
            }
            const float* base = tile + (ch * 16) * FDIM + kc * 4;
            #pragma unroll
            for (int r = 0; r < 16; ++r) {
                ulonglong2 v = *reinterpret_cast<const ulonglong2*>(base + r*FDIM);
                acc[r] = ffma2(v.x, wp0, acc[r]);
                acc[r] = ffma2(v.y, wp1, acc[r]);
            }
        }
        #pragma unroll
        for (int r = 0; r < 16; ++r) {
            int n = n0 + ch * 16 + r;
            if (n < N) {
                float lo, hi; unpack2(acc[r], lo, hi);
                float val = lo + hi;
                if (mode == 0) {
                    dst[n * FDIM + c] = val;
                } else {
                    dst[n * FDIM + c] = xres[n * FDIM + c] + sspf(val + bias[c]);
                }
            }
        }
    }
}

extern "C" __global__ void zero_agg_kernel(int total4) {
    int i = blockIdx.x * blockDim.x + threadIdx.x;
    if (i < total4) {
        float4 z; z.x = 0.f; z.y = 0.f; z.z = 0.f; z.w = 0.f;
        reinterpret_cast<float4*>(g_agg)[i] = z;
    }
}

// ---------------------------------------------------------------------------

static const int SMEM_EDGE = SMEM_EDGE_FLOATS * 4;
static const int SMEM_NODE = 32 * FDIM * 4;

extern "C" void kernel_launch(void* const* d_in, const int* in_sizes, int n_in,
                              void* d_out, int out_size)
{
    const float* x    = (const float*)d_in[0];
    const void*  eidx = d_in[1];
    const float* ew   = (const float*)d_in[2];
    const float* ea   = (const float*)d_in[3];
    const float* w1   = (const float*)d_in[4];
    const float* b1   = (const float*)d_in[5];
    const float* w2   = (const float*)d_in[6];
    const float* b2   = (const float*)d_in[7];
    const float* l1   = (const float*)d_in[8];
    const float* l2   = (const float*)d_in[9];
    const float* l2b  = (const float*)d_in[10];

    const int N = in_sizes[0] / FDIM;     // x is [N,256]
    const int E = in_sizes[1] / 2;        // edge_index is [2,E]

    cudaFuncSetAttribute(edge_kernel, cudaFuncAttributeMaxDynamicSharedMemorySize, SMEM_EDGE);
    cudaFuncSetAttribute(node_gemm,   cudaFuncAttributeMaxDynamicSharedMemorySize, SMEM_NODE);

    int count64 = E / 2 < 32 ? E / 2 : 32;
    detect_idx_kernel<<<1, 32>>>((const long long*)eidx, count64, N);      // 0
    convert_idx_kernel<<<(E + 255) / 256, 256>>>(eidx, E, N);              // 1

    const int total4 = (N * FDIM) / 4;
    zero_agg_kernel<<<(total4 + 255) / 256, 256>>>(total4);                // 2

    // xs = x @ lin1_w  -> g_xs
    node_gemm<<<(N + 31) / 32, 256, SMEM_NODE>>>(x, l1, nullptr, nullptr,  // 3
                                                 nullptr, N, 0);

    warm_kernel<<<FDIM * FDIM / 256, 256>>>(w2);                           // 4

    // fused edge MLP + cutoff + gather + scatter-add
    edge_kernel<<<(E + TILE_E - 1) / TILE_E, 256, SMEM_EDGE>>>(            // 5 (ncu)
        ew, ea, w1, b1, w2, b2, E);

    // out = x + ssp(agg @ lin2_w + lin2_b)
    node_gemm<<<(N + 31) / 32, 256, SMEM_NODE>>>(nullptr, l2, l2b, x,      // 6
                                                 (float*)d_out, N, 1);
}

// round 12
// speedup vs baseline: 1.3775x; 1.2915x over previous
#include <cuda_runtime.h>
#include <cuda_bf16.h>
#include <cstdint>

// ---------------------------------------------------------------------------
// InteractionBlock (SchNet CFConv).  R12: stage-B edge GEMM on tensor cores
// via base-ISA mma.sync.m16n8k16.bf16 (sm_103 base target — tcgen05 is not
// available through this toolchain).  bf16x3 split => fp32-accurate.
// 64 edges/CTA, 256 thr, accumulators in registers, cp.async-double-buffered
// w2^T chunks, epilogue scatters straight from D fragments.
// ---------------------------------------------------------------------------

#define FDIM 256
#define GDIM 50

#define NMAX 10240
#define EMAX 330000
__device__ __align__(16) float g_xs[NMAX * FDIM];
__device__ __align__(16) float g_agg[NMAX * FDIM];
__device__ int   g_si[EMAX];
__device__ int   g_sj[EMAX];
__device__ int   g_idx64;
// w2 transposed + bf16-split: [kc 8][n 256][kk 32]
__device__ __align__(16) __nv_bfloat16 g_w2t_hi[8 * 256 * 32];
__device__ __align__(16) __nv_bfloat16 g_w2t_lo[8 * 256 * 32];

typedef unsigned long long u64;

// ---- packed f32x2 helpers --------------------------------------------------
__device__ __forceinline__ u64 pack2(float lo, float hi) {
    u64 r; asm("mov.b64 %0, {%1, %2};" : "=l"(r) : "f"(lo), "f"(hi)); return r;
}
__device__ __forceinline__ void unpack2(u64 v, float& lo, float& hi) {
    asm("mov.b64 {%0, %1}, %2;" : "=f"(lo), "=f"(hi) : "l"(v));
}
__device__ __forceinline__ u64 ffma2(u64 a, u64 b, u64 c) {
    u64 d; asm("fma.rn.f32x2 %0, %1, %2, %3;" : "=l"(d) : "l"(a), "l"(b), "l"(c)); return d;
}
__device__ __forceinline__ float sspf(float v) {
    return fmaxf(v, 0.f) + log1pf(expf(-fabsf(v))) - 0.69314718055994530942f;
}

// ---- base-ISA tensor core mma ---------------------------------------------
__device__ __forceinline__ void mma16816(float* d,
    uint32_t a0, uint32_t a1, uint32_t a2, uint32_t a3,
    uint32_t b0, uint32_t b1)
{
    asm volatile(
        "mma.sync.aligned.m16n8k16.row.col.f32.bf16.bf16.f32 "
        "{%0,%1,%2,%3}, {%4,%5,%6,%7}, {%8,%9}, {%0,%1,%2,%3};"
        : "+f"(d[0]), "+f"(d[1]), "+f"(d[2]), "+f"(d[3])
        : "r"(a0), "r"(a1), "r"(a2), "r"(a3), "r"(b0), "r"(b1));
}

// ---- cp.async --------------------------------------------------------------
__device__ __forceinline__ void cp16(uint32_t smem_dst, const void* gsrc) {
    asm volatile("cp.async.cg.shared.global [%0], [%1], 16;"
                 :: "r"(smem_dst), "l"(gsrc) : "memory");
}
__device__ __forceinline__ void cp_commit() {
    asm volatile("cp.async.commit_group;" ::: "memory");
}
template <int N> __device__ __forceinline__ void cp_wait() {
    asm volatile("cp.async.wait_group %0;" :: "n"(N) : "memory");
}
__device__ __forceinline__ uint32_t smem_u32(const void* p) {
    uint32_t a;
    asm("{ .reg .u64 t; cvta.to.shared.u64 t, %1; cvt.u32.u64 %0, t; }"
        : "=r"(a) : "l"(p));
    return a;
}

// ---------------------------------------------------------------------------
extern "C" __global__ void detect_idx_kernel(const long long* __restrict__ p,
                                             int count64, int N)
{
    int lane = threadIdx.x;
    int ok = 1;
    if (lane < count64) {
        long long v = p[lane];
        ok = (v >= 0 && v < (long long)N) ? 1 : 0;
    }
    unsigned all = __ballot_sync(0xFFFFFFFFu, ok);
    if (lane == 0) g_idx64 = (all == 0xFFFFFFFFu) ? 1 : 0;
}

extern "C" __global__ void convert_idx_kernel(const void* __restrict__ p, int E, int N)
{
    int e = blockIdx.x * blockDim.x + threadIdx.x;
    if (e >= E) return;
    int iv, jv;
    if (g_idx64) {
        const long long* q = (const long long*)p;
        iv = (int)q[e]; jv = (int)q[E + e];
    } else {
        const int* q = (const int*)p;
        iv = q[e]; jv = q[E + e];
    }
    g_si[e] = min(max(iv, 0), N - 1);
    g_sj[e] = min(max(jv, 0), N - 1);
}

// transpose + bf16-split w2 into [kc][n][kk] chunks
extern "C" __global__ void prep_w2t(const float* __restrict__ w2) {
    int idx = blockIdx.x * 256 + threadIdx.x;    // 65536
    int k = idx >> 8, n = idx & 255;
    float v = w2[k * 256 + n];
    __nv_bfloat16 hi = __float2bfloat16(v);
    __nv_bfloat16 lo = __float2bfloat16(v - __bfloat162float(hi));
    int off = (k >> 5) * (256 * 32) + n * 32 + (k & 31);
    g_w2t_hi[off] = hi;
    g_w2t_lo[off] = lo;
}

// L2 warm for w2t (also a launch-index filler before the edge kernel)
extern "C" __global__ void warm_kernel(int n) {
    int i = blockIdx.x * blockDim.x + threadIdx.x;
    if (i < n) {
        unsigned a = ((const unsigned*)g_w2t_hi)[i];
        unsigned b = ((const unsigned*)g_w2t_lo)[i];
        if (blockIdx.x == 0x7FFFFFF0) g_agg[0] = (float)(a + b);  // never
    }
}

extern "C" __global__ void zero_agg_kernel(int total4) {
    int i = blockIdx.x * blockDim.x + threadIdx.x;
    if (i < total4) {
        float4 z; z.x = 0.f; z.y = 0.f; z.z = 0.f; z.w = 0.f;
        reinterpret_cast<float4*>(g_agg)[i] = z;
    }
}

// ---------------------------------------------------------------------------
// Fused edge kernel: 64 edges/CTA, 256 threads (8 warps), 1 CTA/SM.
// smem (bytes):
//   HID_HI [0,33792)      64 rows x 264 bf16 (stride 528 B)
//   HID_LO [33792,67584)
//   BBUF   [67584,149504) 2 bufs x (hi 20480 + lo 20480); B row stride 80 B
//   EA_S   [149504,163840) 64x56 fp32
//   SC/SI/SJ aux
// ---------------------------------------------------------------------------
#define EDG      64
#define HID_STRB 528
#define HID_HI   0
#define HID_LO   33792
#define BBUF     67584
#define B_STRB   80
#define BUF_SZ   40960         // hi+lo per buffer
#define EA_S     149504
#define SC_OFF   163840
#define SI_OFF   164096
#define SJ_OFF   164352
#define SMEM_EDGE 164608

extern "C" __global__ void __launch_bounds__(256, 1)
edge_kernel(const float* __restrict__ ew,
            const float* __restrict__ ea,
            const float* __restrict__ w1,
            const float* __restrict__ b1,
            const float* __restrict__ b2,
            int E)
{
    extern __shared__ char smem_raw[];
    const uint32_t sbase = smem_u32(smem_raw);
    const int tid  = threadIdx.x;
    const int e0   = blockIdx.x * EDG;

    float* ea_s = (float*)(smem_raw + EA_S);
    float* sC   = (float*)(smem_raw + SC_OFF);
    int*   si   = (int*)(smem_raw + SI_OFF);
    int*   sj   = (int*)(smem_raw + SJ_OFF);

    // indices + cutoff
    if (tid < EDG) {
        int e = e0 + tid;
        float C = 0.f; int iv = 0, jv = 0;
        if (e < E) {
            iv = g_si[e]; jv = g_sj[e];
            float a = ew[e*3+0], b = ew[e*3+1], c2 = ew[e*3+2];
            float d = sqrtf(a*a + b*b + c2*c2);
            if (d <= 2.0f) C = 0.5f * (cosf(d * 1.57079632679489662f) + 1.f);
        }
        si[tid] = iv; sj[tid] = jv; sC[tid] = C;
    }

    // edge_attr tile [64][56] fp32, zero-padded
    for (int idx = tid; idx < EDG * 56; idx += 256) {
        int r = idx / 56, k = idx % 56;
        float v = 0.f;
        int e = e0 + r;
        if (k < GDIM && e < E) v = ea[e * GDIM + k];
        ea_s[idx] = v;
    }

    // prefetch B chunks 0 and 1 while stage A computes
    // per chunk: hi = 256 rows x 64B (4x16B), lo same. 256 thr x 4 transfers.
    {
        #pragma unroll
        for (int cc = 0; cc < 2; ++cc) {
            int n = tid >> 2, p = tid & 3;       // wait: 1024 transfers, 4/thread
            #pragma unroll
            for (int q = 0; q < 4; ++q) {
                int t = q * 256 + tid;            // [0,1024)
                int nn = t >> 2, pp = t & 3;
                uint32_t dh = sbase + BBUF + cc * BUF_SZ + nn * B_STRB + pp * 16;
                uint32_t dl = dh + 20480;
                cp16(dh, (const char*)g_w2t_hi + cc * 16384 + nn * 64 + pp * 16);
                cp16(dl, (const char*)g_w2t_lo + cc * 16384 + nn * 64 + pp * 16);
            }
            cp_commit();
            (void)n; (void)p;
        }
    }
    __syncthreads();

    // ---------------- Stage A (scalar f32x2): hid = ssp(ea@W1+b1) ----------
    {
        const int c = tid;
        u64 wp[26];
        #pragma unroll
        for (int kc = 0; kc < 13; ++kc) {
            float w0 = (4*kc+0 < GDIM) ? w1[(4*kc+0)*FDIM + c] : 0.f;
            float wv1 = (4*kc+1 < GDIM) ? w1[(4*kc+1)*FDIM + c] : 0.f;
            float w2v = (4*kc+2 < GDIM) ? w1[(4*kc+2)*FDIM + c] : 0.f;
            float w3 = (4*kc+3 < GDIM) ? w1[(4*kc+3)*FDIM + c] : 0.f;
            wp[2*kc]   = pack2(w0, wv1);
            wp[2*kc+1] = pack2(w2v, w3);
        }
        const float b1c = b1[c];
        #pragma unroll 1
        for (int ch = 0; ch < 4; ++ch) {
            u64 acc[16];
            #pragma unroll
            for (int e = 0; e < 16; ++e) acc[e] = 0ULL;
            #pragma unroll
            for (int kc = 0; kc < 13; ++kc) {
                const float* base = ea_s + (ch * 16) * 56 + kc * 4;
                #pragma unroll
                for (int e = 0; e < 16; ++e) {
                    ulonglong2 v = *reinterpret_cast<const ulonglong2*>(base + e * 56);
                    acc[e] = ffma2(v.x, wp[2*kc],   acc[e]);
                    acc[e] = ffma2(v.y, wp[2*kc+1], acc[e]);
                }
            }
            #pragma unroll
            for (int e = 0; e < 16; ++e) {
                float lo, hi; unpack2(acc[e], lo, hi);
                float v = sspf(lo + hi + b1c);
                __nv_bfloat16 vh = __float2bfloat16(v);
                __nv_bfloat16 vl = __float2bfloat16(v - __bfloat162float(vh));
                int row = ch * 16 + e;
                *(__nv_bfloat16*)(smem_raw + HID_HI + row * HID_STRB + c * 2) = vh;
                *(__nv_bfloat16*)(smem_raw + HID_LO + row * HID_STRB + c * 2) = vl;
            }
        }
    }
    __syncthreads();   // hid ready for all warps

    // ---------------- Stage B: mma.sync bf16x3, D in registers -------------
    const int lane = tid & 31;
    const int w    = tid >> 5;          // warp owns cols [w*32, w*32+32)
    const int lp   = lane & 3;
    const int lg   = lane >> 2;

    float acc[4][4][4];                 // [m-tile][n-tile][frag]
    #pragma unroll
    for (int m = 0; m < 4; ++m)
        #pragma unroll
        for (int t = 0; t < 4; ++t)
            #pragma unroll
            for (int q = 0; q < 4; ++q) acc[m][t][q] = 0.f;

    #pragma unroll 1
    for (int kc = 0; kc < 8; ++kc) {
        if (kc == 7) cp_wait<0>(); else cp_wait<1>();
        __syncthreads();                           // chunk kc visible to all

        const char* Bbase = smem_raw + BBUF + (kc & 1) * BUF_SZ;
        #pragma unroll
        for (int ks = 0; ks < 2; ++ks) {
            #pragma unroll
            for (int term = 0; term < 3; ++term) {
                const char* Ab = smem_raw + (term == 2 ? HID_LO : HID_HI);
                const char* Bb = Bbase + (term == 1 ? 20480 : 0);
                uint32_t bfr[4][2];
                #pragma unroll
                for (int t = 0; t < 4; ++t) {
                    const char* bp = Bb + (w*32 + t*8 + lg) * B_STRB + ks*32 + lp*4;
                    bfr[t][0] = *(const uint32_t*)bp;
                    bfr[t][1] = *(const uint32_t*)(bp + 16);
                }
                #pragma unroll
                for (int m = 0; m < 4; ++m) {
                    const char* ap = Ab + (m*16 + lg) * HID_STRB + kc*64 + ks*32 + lp*4;
                    uint32_t a0 = *(const uint32_t*)ap;
                    uint32_t a1 = *(const uint32_t*)(ap + 8 * HID_STRB);
                    uint32_t a2 = *(const uint32_t*)(ap + 16);
                    uint32_t a3 = *(const uint32_t*)(ap + 8 * HID_STRB + 16);
                    #pragma unroll
                    for (int t = 0; t < 4; ++t)
                        mma16816(acc[m][t], a0, a1, a2, a3, bfr[t][0], bfr[t][1]);
                }
            }
        }
        __syncthreads();                           // all done with buf[kc&1]
        if (kc + 2 < 8) {                          // refill it with chunk kc+2
            int cc = kc + 2;
            #pragma unroll
            for (int q = 0; q < 4; ++q) {
                int t = q * 256 + tid;
                int nn = t >> 2, pp = t & 3;
                uint32_t dh = sbase + BBUF + (cc & 1) * BUF_SZ + nn * B_STRB + pp * 16;
                cp16(dh,         (const char*)g_w2t_hi + cc * 16384 + nn * 64 + pp * 16);
                cp16(dh + 20480, (const char*)g_w2t_lo + cc * 16384 + nn * 64 + pp * 16);
            }
            cp_commit();
        }
    }

    // ---------------- epilogue: (D+b2)*C*xs[j] -> atomicAdd agg[i] ---------
    float b2a[4], b2b[4];
    #pragma unroll
    for (int t = 0; t < 4; ++t) {
        int c0 = w*32 + t*8 + 2*lp;
        b2a[t] = b2[c0];
        b2b[t] = b2[c0 + 1];
    }
    #pragma unroll
    for (int m = 0; m < 4; ++m) {
        #pragma unroll
        for (int half = 0; half < 2; ++half) {
            int e = m*16 + lg + half*8;
            float Ce = sC[e];
            if (Ce != 0.f) {
                int ii = si[e], jj = sj[e];
                const float* xr = g_xs + (size_t)jj * FDIM;
                float*       ar = g_agg + (size_t)ii * FDIM;
                #pragma unroll
                for (int t = 0; t < 4; ++t) {
                    int c0 = w*32 + t*8 + 2*lp;
                    float2 xv = *(const float2*)(xr + c0);
                    float d0 = acc[m][t][half*2 + 0];
                    float d1 = acc[m][t][half*2 + 1];
                    atomicAdd(&ar[c0],     (d0 + b2a[t]) * Ce * xv.x);
                    atomicAdd(&ar[c0 + 1], (d1 + b2b[t]) * Ce * xv.y);
                }
            }
        }
    }
}

// ---------------------------------------------------------------------------
// Node GEMM (scalar f32x2, proven). mode 0: g_xs = in @ w.
// mode 1: out = xres + ssp(g_agg @ w + bias).
// ---------------------------------------------------------------------------
extern "C" __global__ void __launch_bounds__(256, 3)
node_gemm(const float* __restrict__ in,
          const float* __restrict__ w,
          const float* __restrict__ bias,
          const float* __restrict__ xres,
          float* __restrict__ out,
          int N, int mode)
{
    extern __shared__ float tile[];          // 32*256 floats
    const int tid = threadIdx.x;
    const int n0  = blockIdx.x * 32;

    const float* src = (mode == 0) ? in : (const float*)g_agg;
    float* dst       = (mode == 0) ? g_xs : out;

    {
        const float4* s4 = reinterpret_cast<const float4*>(src);
        float4* t4 = reinterpret_cast<float4*>(tile);
        #pragma unroll
        for (int q = 0; q < 8; ++q) {
            int idx = q * 256 + tid;
            int r = idx >> 6;
            float4 v = make_float4(0.f, 0.f, 0.f, 0.f);
            if (n0 + r < N) v = s4[(size_t)(n0 + r) * 64 + (idx & 63)];
            t4[idx] = v;
        }
    }
    __syncthreads();

    const int c = tid;
    #pragma unroll 1
    for (int ch = 0; ch < 2; ++ch) {
        u64 acc[16];
        #pragma unroll
        for (int r = 0; r < 16; ++r) acc[r] = 0ULL;

        float a0 = w[0*FDIM + c], a1 = w[1*FDIM + c];
        float a2 = w[2*FDIM + c], a3 = w[3*FDIM + c];
        float p0 = w[4*FDIM + c], p1 = w[5*FDIM + c];
        float p2 = w[6*FDIM + c], p3 = w[7*FDIM + c];
        #pragma unroll 1
        for (int kc = 0; kc < 64; ++kc) {
            u64 wp0 = pack2(a0, a1);
            u64 wp1 = pack2(a2, a3);
            a0 = p0; a1 = p1; a2 = p2; a3 = p3;
            if (kc + 2 < 64) {
                int k0 = (kc + 2) * 4;
                p0 = w[(k0+0)*FDIM + c]; p1 = w[(k0+1)*FDIM + c];
                p2 = w[(k0+2)*FDIM + c]; p3 = w[(k0+3)*FDIM + c];
            }
            const float* base = tile + (ch * 16) * FDIM + kc * 4;
            #pragma unroll
            for (int r = 0; r < 16; ++r) {
                ulonglong2 v = *reinterpret_cast<const ulonglong2*>(base + r*FDIM);
                acc[r] = ffma2(v.x, wp0, acc[r]);
                acc[r] = ffma2(v.y, wp1, acc[r]);
            }
        }
        #pragma unroll
        for (int r = 0; r < 16; ++r) {
            int n = n0 + ch * 16 + r;
            if (n < N) {
                float lo, hi; unpack2(acc[r], lo, hi);
                float val = lo + hi;
                if (mode == 0) dst[n * FDIM + c] = val;
                else dst[n * FDIM + c] = xres[n * FDIM + c] + sspf(val + bias[c]);
            }
        }
    }
}

// ---------------------------------------------------------------------------

static const int SMEM_NODE = 32 * FDIM * 4;

extern "C" void kernel_launch(void* const* d_in, const int* in_sizes, int n_in,
                              void* d_out, int out_size)
{
    const float* x    = (const float*)d_in[0];
    const void*  eidx = d_in[1];
    const float* ew   = (const float*)d_in[2];
    const float* ea   = (const float*)d_in[3];
    const float* w1   = (const float*)d_in[4];
    const float* b1   = (const float*)d_in[5];
    const float* w2   = (const float*)d_in[6];
    const float* b2   = (const float*)d_in[7];
    const float* l1   = (const float*)d_in[8];
    const float* l2   = (const float*)d_in[9];
    const float* l2b  = (const float*)d_in[10];

    const int N = in_sizes[0] / FDIM;     // x is [N,256]
    const int E = in_sizes[1] / 2;        // edge_index is [2,E]

    cudaFuncSetAttribute(edge_kernel, cudaFuncAttributeMaxDynamicSharedMemorySize, SMEM_EDGE);
    cudaFuncSetAttribute(node_gemm,   cudaFuncAttributeMaxDynamicSharedMemorySize, SMEM_NODE);

    int count64 = E / 2 < 32 ? E / 2 : 32;
    detect_idx_kernel<<<1, 32>>>((const long long*)eidx, count64, N);          // 0
    convert_idx_kernel<<<(E + 255) / 256, 256>>>(eidx, E, N);                  // 1

    const int total4 = (N * FDIM) / 4;
    zero_agg_kernel<<<(total4 + 255) / 256, 256>>>(total4);                    // 2

    prep_w2t<<<256, 256>>>(w2);                                                // 3

    // xs = x @ lin1_w  -> g_xs
    node_gemm<<<(N + 31) / 32, 256, SMEM_NODE>>>(x, l1, nullptr, nullptr,      // 4
                                                 nullptr, N, 0);

    warm_kernel<<<128, 256>>>(32768);                                          // 5

    // fused edge MLP (stage A scalar, stage B mma.sync) + scatter-add
    edge_kernel<<<(E + EDG - 1) / EDG, 256, SMEM_EDGE>>>(ew, ea, w1, b1, b2, E); // 6

    // out = x + ssp(agg @ lin2_w + lin2_b)
    node_gemm<<<(N + 31) / 32, 256, SMEM_NODE>>>(nullptr, l2, l2b, x,          // 7
                                                 (float*)d_out, N, 1);
}

// round 13
// speedup vs baseline: 1.5309x; 1.1114x over previous
#include <cuda_runtime.h>
#include <cuda_bf16.h>
#include <cstdint>

// ---------------------------------------------------------------------------
// InteractionBlock (SchNet CFConv).  R13: R12's mma.sync bf16x3 edge kernel
// restructured for occupancy: 32 edges/CTA, 16-k B chunks (48B row stride,
// conflict-free), ~90KB smem -> 2 CTAs/SM (16 warps). Fast-math ssp/cos.
// ---------------------------------------------------------------------------

#define FDIM 256
#define GDIM 50

#define NMAX 10240
#define EMAX 330000
__device__ __align__(16) float g_xs[NMAX * FDIM];
__device__ __align__(16) float g_agg[NMAX * FDIM];
__device__ int   g_si[EMAX];
__device__ int   g_sj[EMAX];
__device__ int   g_idx64;
// w2 transposed + bf16-split: [kc 16][n 256][kk 16]
__device__ __align__(16) __nv_bfloat16 g_w2t_hi[16 * 256 * 16];
__device__ __align__(16) __nv_bfloat16 g_w2t_lo[16 * 256 * 16];

typedef unsigned long long u64;

// ---- packed f32x2 helpers --------------------------------------------------
__device__ __forceinline__ u64 pack2(float lo, float hi) {
    u64 r; asm("mov.b64 %0, {%1, %2};" : "=l"(r) : "f"(lo), "f"(hi)); return r;
}
__device__ __forceinline__ void unpack2(u64 v, float& lo, float& hi) {
    asm("mov.b64 {%0, %1}, %2;" : "=f"(lo), "=f"(hi) : "l"(v));
}
__device__ __forceinline__ u64 ffma2(u64 a, u64 b, u64 c) {
    u64 d; asm("fma.rn.f32x2 %0, %1, %2, %3;" : "=l"(d) : "l"(a), "l"(b), "l"(c)); return d;
}
// fast shifted softplus: max(x,0)+log(1+exp(-|x|))-ln2  (MUFU; ~1e-7 abs err)
__device__ __forceinline__ float sspf(float v) {
    float t = __expf(-fabsf(v));
    return fmaxf(v, 0.f) + __logf(1.f + t) - 0.69314718055994530942f;
}

// ---- base-ISA tensor core mma ---------------------------------------------
__device__ __forceinline__ void mma16816(float* d,
    uint32_t a0, uint32_t a1, uint32_t a2, uint32_t a3,
    uint32_t b0, uint32_t b1)
{
    asm volatile(
        "mma.sync.aligned.m16n8k16.row.col.f32.bf16.bf16.f32 "
        "{%0,%1,%2,%3}, {%4,%5,%6,%7}, {%8,%9}, {%0,%1,%2,%3};"
        : "+f"(d[0]), "+f"(d[1]), "+f"(d[2]), "+f"(d[3])
        : "r"(a0), "r"(a1), "r"(a2), "r"(a3), "r"(b0), "r"(b1));
}

// ---- cp.async --------------------------------------------------------------
__device__ __forceinline__ void cp16(uint32_t smem_dst, const void* gsrc) {
    asm volatile("cp.async.cg.shared.global [%0], [%1], 16;"
                 :: "r"(smem_dst), "l"(gsrc) : "memory");
}
__device__ __forceinline__ void cp_commit() {
    asm volatile("cp.async.commit_group;" ::: "memory");
}
template <int N> __device__ __forceinline__ void cp_wait() {
    asm volatile("cp.async.wait_group %0;" :: "n"(N) : "memory");
}
__device__ __forceinline__ uint32_t smem_u32(const void* p) {
    uint32_t a;
    asm("{ .reg .u64 t; cvta.to.shared.u64 t, %1; cvt.u32.u64 %0, t; }"
        : "=r"(a) : "l"(p));
    return a;
}

// ---------------------------------------------------------------------------
extern "C" __global__ void detect_idx_kernel(const long long* __restrict__ p,
                                             int count64, int N)
{
    int lane = threadIdx.x;
    int ok = 1;
    if (lane < count64) {
        long long v = p[lane];
        ok = (v >= 0 && v < (long long)N) ? 1 : 0;
    }
    unsigned all = __ballot_sync(0xFFFFFFFFu, ok);
    if (lane == 0) g_idx64 = (all == 0xFFFFFFFFu) ? 1 : 0;
}

extern "C" __global__ void convert_idx_kernel(const void* __restrict__ p, int E, int N)
{
    int e = blockIdx.x * blockDim.x + threadIdx.x;
    if (e >= E) return;
    int iv, jv;
    if (g_idx64) {
        const long long* q = (const long long*)p;
        iv = (int)q[e]; jv = (int)q[E + e];
    } else {
        const int* q = (const int*)p;
        iv = q[e]; jv = q[E + e];
    }
    g_si[e] = min(max(iv, 0), N - 1);
    g_sj[e] = min(max(jv, 0), N - 1);
}

// transpose + bf16-split w2 into [kc 16][n 256][kk 16]
extern "C" __global__ void prep_w2t(const float* __restrict__ w2) {
    int idx = blockIdx.x * 256 + threadIdx.x;    // 65536
    int k = idx >> 8, n = idx & 255;
    float v = w2[k * 256 + n];
    __nv_bfloat16 hi = __float2bfloat16(v);
    __nv_bfloat16 lo = __float2bfloat16(v - __bfloat162float(hi));
    int off = (k >> 4) * (256 * 16) + n * 16 + (k & 15);
    g_w2t_hi[off] = hi;
    g_w2t_lo[off] = lo;
}

// L2 warm for w2t
extern "C" __global__ void warm_kernel(int n) {
    int i = blockIdx.x * blockDim.x + threadIdx.x;
    if (i < n) {
        unsigned a = ((const unsigned*)g_w2t_hi)[i];
        unsigned b = ((const unsigned*)g_w2t_lo)[i];
        if (blockIdx.x == 0x7FFFFFF0) g_agg[0] = (float)(a + b);  // never
    }
}

extern "C" __global__ void zero_agg_kernel(int total4) {
    int i = blockIdx.x * blockDim.x + threadIdx.x;
    if (i < total4) {
        float4 z; z.x = 0.f; z.y = 0.f; z.z = 0.f; z.w = 0.f;
        reinterpret_cast<float4*>(g_agg)[i] = z;
    }
}

// ---------------------------------------------------------------------------
// Fused edge kernel: 32 edges/CTA, 256 threads (8 warps), 2 CTAs/SM.
// smem (bytes):
//   HID_HI [0,16896)       32 rows x 264 bf16 (stride 528 B)
//   HID_LO [16896,33792)
//   BBUF   [33792,82944)   2 bufs x (hi 12288 + lo 12288); B row stride 48 B
//   EA_S   [82944,90112)   32x56 fp32
//   SC/SI/SJ aux -> total 90496
// ---------------------------------------------------------------------------
#define EDG      32
#define HID_STRB 528
#define HID_HI   0
#define HID_LO   16896
#define BBUF     33792
#define B_STRB   48
#define B_COMP   12288         // one component (hi or lo) per buffer
#define BUF_SZ   24576         // hi+lo per buffer
#define EA_S     82944
#define SC_OFF   90112
#define SI_OFF   90240
#define SJ_OFF   90368
#define SMEM_EDGE 90496

// one B chunk = 256 rows x 32 B data (+16 pad), both components: 1024 cp16
__device__ __forceinline__ void load_b_chunk(uint32_t sbase, int buf, int cc, int tid)
{
    uint32_t dbase = sbase + BBUF + buf * BUF_SZ;
    const char* sh = (const char*)g_w2t_hi + cc * 8192;
    const char* sl = (const char*)g_w2t_lo + cc * 8192;
    #pragma unroll
    for (int q = 0; q < 2; ++q) {
        int t = q * 256 + tid;               // [0,512): hi
        int row = t >> 1, seg = t & 1;
        cp16(dbase + row * B_STRB + seg * 16, sh + row * 32 + seg * 16);
    }
    #pragma unroll
    for (int q = 0; q < 2; ++q) {
        int t = q * 256 + tid;               // [0,512): lo
        int row = t >> 1, seg = t & 1;
        cp16(dbase + B_COMP + row * B_STRB + seg * 16, sl + row * 32 + seg * 16);
    }
}

extern "C" __global__ void __launch_bounds__(256, 2)
edge_kernel(const float* __restrict__ ew,
            const float* __restrict__ ea,
            const float* __restrict__ w1,
            const float* __restrict__ b1,
            const float* __restrict__ b2,
            int E)
{
    extern __shared__ char smem_raw[];
    const uint32_t sbase = smem_u32(smem_raw);
    const int tid  = threadIdx.x;
    const int e0   = blockIdx.x * EDG;

    float* ea_s = (float*)(smem_raw + EA_S);
    float* sC   = (float*)(smem_raw + SC_OFF);
    int*   si   = (int*)(smem_raw + SI_OFF);
    int*   sj   = (int*)(smem_raw + SJ_OFF);

    // indices + cutoff
    if (tid < EDG) {
        int e = e0 + tid;
        float C = 0.f; int iv = 0, jv = 0;
        if (e < E) {
            iv = g_si[e]; jv = g_sj[e];
            float a = ew[e*3+0], b = ew[e*3+1], c2 = ew[e*3+2];
            float d = sqrtf(a*a + b*b + c2*c2);
            if (d <= 2.0f) C = 0.5f * (__cosf(d * 1.57079632679489662f) + 1.f);
        }
        si[tid] = iv; sj[tid] = jv; sC[tid] = C;
    }

    // edge_attr tile [32][56] fp32, zero-padded
    for (int idx = tid; idx < EDG * 56; idx += 256) {
        int r = idx / 56, k = idx % 56;
        float v = 0.f;
        int e = e0 + r;
        if (k < GDIM && e < E) v = ea[e * GDIM + k];
        ea_s[idx] = v;
    }

    // prefetch B chunks 0,1 (overlap with stage A)
    load_b_chunk(sbase, 0, 0, tid); cp_commit();
    load_b_chunk(sbase, 1, 1, tid); cp_commit();
    __syncthreads();

    // ---------------- Stage A (scalar f32x2): hid = ssp(ea@W1+b1) ----------
    {
        const int c = tid;
        u64 wp[26];
        #pragma unroll
        for (int kc = 0; kc < 13; ++kc) {
            float w0 = (4*kc+0 < GDIM) ? w1[(4*kc+0)*FDIM + c] : 0.f;
            float wv1 = (4*kc+1 < GDIM) ? w1[(4*kc+1)*FDIM + c] : 0.f;
            float w2v = (4*kc+2 < GDIM) ? w1[(4*kc+2)*FDIM + c] : 0.f;
            float w3 = (4*kc+3 < GDIM) ? w1[(4*kc+3)*FDIM + c] : 0.f;
            wp[2*kc]   = pack2(w0, wv1);
            wp[2*kc+1] = pack2(w2v, w3);
        }
        const float b1c = b1[c];
        #pragma unroll 1
        for (int ch = 0; ch < 2; ++ch) {
            u64 acc[16];
            #pragma unroll
            for (int e = 0; e < 16; ++e) acc[e] = 0ULL;
            #pragma unroll
            for (int kc = 0; kc < 13; ++kc) {
                const float* base = ea_s + (ch * 16) * 56 + kc * 4;
                #pragma unroll
                for (int e = 0; e < 16; ++e) {
                    ulonglong2 v = *reinterpret_cast<const ulonglong2*>(base + e * 56);
                    acc[e] = ffma2(v.x, wp[2*kc],   acc[e]);
                    acc[e] = ffma2(v.y, wp[2*kc+1], acc[e]);
                }
            }
            #pragma unroll
            for (int e = 0; e < 16; ++e) {
                float lo, hi; unpack2(acc[e], lo, hi);
                float v = sspf(lo + hi + b1c);
                __nv_bfloat16 vh = __float2bfloat16(v);
                __nv_bfloat16 vl = __float2bfloat16(v - __bfloat162float(vh));
                int row = ch * 16 + e;
                *(__nv_bfloat16*)(smem_raw + HID_HI + row * HID_STRB + c * 2) = vh;
                *(__nv_bfloat16*)(smem_raw + HID_LO + row * HID_STRB + c * 2) = vl;
            }
        }
    }
    __syncthreads();   // hid ready

    // ---------------- Stage B: mma.sync bf16x3, D in registers -------------
    const int lane = tid & 31;
    const int w    = tid >> 5;          // warp owns cols [w*32, w*32+32)
    const int lp   = lane & 3;
    const int lg   = lane >> 2;

    float acc[2][4][4];                 // [m-tile][n-tile][frag]
    #pragma unroll
    for (int m = 0; m < 2; ++m)
        #pragma unroll
        for (int t = 0; t < 4; ++t)
            #pragma unroll
            for (int q = 0; q < 4; ++q) acc[m][t][q] = 0.f;

    #pragma unroll 1
    for (int kc = 0; kc < 16; ++kc) {
        if (kc == 15) cp_wait<0>(); else cp_wait<1>();
        __syncthreads();                           // chunk kc visible

        const char* Bbase = smem_raw + BBUF + (kc & 1) * BUF_SZ;
        #pragma unroll
        for (int term = 0; term < 3; ++term) {
            const char* Ab = smem_raw + (term == 2 ? HID_LO : HID_HI);
            const char* Bb = Bbase + (term == 1 ? B_COMP : 0);
            uint32_t bfr[4][2];
            #pragma unroll
            for (int t = 0; t < 4; ++t) {
                const char* bp = Bb + (w*32 + t*8 + lg) * B_STRB + lp*4;
                bfr[t][0] = *(const uint32_t*)bp;
                bfr[t][1] = *(const uint32_t*)(bp + 16);
            }
            #pragma unroll
            for (int m = 0; m < 2; ++m) {
                const char* ap = Ab + (m*16 + lg) * HID_STRB + kc*32 + lp*4;
                uint32_t a0 = *(const uint32_t*)ap;
                uint32_t a1 = *(const uint32_t*)(ap + 8 * HID_STRB);
                uint32_t a2 = *(const uint32_t*)(ap + 16);
                uint32_t a3 = *(const uint32_t*)(ap + 8 * HID_STRB + 16);
                #pragma unroll
                for (int t = 0; t < 4; ++t)
                    mma16816(acc[m][t], a0, a1, a2, a3, bfr[t][0], bfr[t][1]);
            }
        }
        __syncthreads();                           // done with buf[kc&1]
        if (kc + 2 < 16) {
            load_b_chunk(sbase, kc & 1, kc + 2, tid);
            cp_commit();
        }
    }

    // ---------------- epilogue: (D+b2)*C*xs[j] -> atomicAdd agg[i] ---------
    float b2a[4], b2b[4];
    #pragma unroll
    for (int t = 0; t < 4; ++t) {
        int c0 = w*32 + t*8 + 2*lp;
        b2a[t] = b2[c0];
        b2b[t] = b2[c0 + 1];
    }
    #pragma unroll
    for (int m = 0; m < 2; ++m) {
        #pragma unroll
        for (int half = 0; half < 2; ++half) {
            int e = m*16 + lg + half*8;
            float Ce = sC[e];
            if (Ce != 0.f) {
                int ii = si[e], jj = sj[e];
                const float* xr = g_xs + (size_t)jj * FDIM;
                float*       ar = g_agg + (size_t)ii * FDIM;
                #pragma unroll
                for (int t = 0; t < 4; ++t) {
                    int c0 = w*32 + t*8 + 2*lp;
                    float2 xv = *(const float2*)(xr + c0);
                    float d0 = acc[m][t][half*2 + 0];
                    float d1 = acc[m][t][half*2 + 1];
                    atomicAdd(&ar[c0],     (d0 + b2a[t]) * Ce * xv.x);
                    atomicAdd(&ar[c0 + 1], (d1 + b2b[t]) * Ce * xv.y);
                }
            }
        }
    }
}

// ---------------------------------------------------------------------------
// Node GEMM (scalar f32x2). mode 0: g_xs = in @ w.
// mode 1: out = xres + ssp(g_agg @ w + bias).
// ---------------------------------------------------------------------------
extern "C" __global__ void __launch_bounds__(256, 3)
node_gemm(const float* __restrict__ in,
          const float* __restrict__ w,
          const float* __restrict__ bias,
          const float* __restrict__ xres,
          float* __restrict__ out,
          int N, int mode)
{
    extern __shared__ float tile[];          // 32*256 floats
    const int tid = threadIdx.x;
    const int n0  = blockIdx.x * 32;

    const float* src = (mode == 0) ? in : (const float*)g_agg;
    float* dst       = (mode == 0) ? g_xs : out;

    {
        const float4* s4 = reinterpret_cast<const float4*>(src);
        float4* t4 = reinterpret_cast<float4*>(tile);
        #pragma unroll
        for (int q = 0; q < 8; ++q) {
            int idx = q * 256 + tid;
            int r = idx >> 6;
            float4 v = make_float4(0.f, 0.f, 0.f, 0.f);
            if (n0 + r < N) v = s4[(size_t)(n0 + r) * 64 + (idx & 63)];
            t4[idx] = v;
        }
    }
    __syncthreads();

    const int c = tid;
    #pragma unroll 1
    for (int ch = 0; ch < 2; ++ch) {
        u64 acc[16];
        #pragma unroll
        for (int r = 0; r < 16; ++r) acc[r] = 0ULL;

        float a0 = w[0*FDIM + c], a1 = w[1*FDIM + c];
        float a2 = w[2*FDIM + c], a3 = w[3*FDIM + c];
        float p0 = w[4*FDIM + c], p1 = w[5*FDIM + c];
        float p2 = w[6*FDIM + c], p3 = w[7*FDIM + c];
        #pragma unroll 1
        for (int kc = 0; kc < 64; ++kc) {
            u64 wp0 = pack2(a0, a1);
            u64 wp1 = pack2(a2, a3);
            a0 = p0; a1 = p1; a2 = p2; a3 = p3;
            if (kc + 2 < 64) {
                int k0 = (kc + 2) * 4;
                p0 = w[(k0+0)*FDIM + c]; p1 = w[(k0+1)*FDIM + c];
                p2 = w[(k0+2)*FDIM + c]; p3 = w[(k0+3)*FDIM + c];
            }
            const float* base = tile + (ch * 16) * FDIM + kc * 4;
            #pragma unroll
            for (int r = 0; r < 16; ++r) {
                ulonglong2 v = *reinterpret_cast<const ulonglong2*>(base + r*FDIM);
                acc[r] = ffma2(v.x, wp0, acc[r]);
                acc[r] = ffma2(v.y, wp1, acc[r]);
            }
        }
        #pragma unroll
        for (int r = 0; r < 16; ++r) {
            int n = n0 + ch * 16 + r;
            if (n < N) {
                float lo, hi; unpack2(acc[r], lo, hi);
                float val = lo + hi;
                if (mode == 0) dst[n * FDIM + c] = val;
                else dst[n * FDIM + c] = xres[n * FDIM + c] + sspf(val + bias[c]);
            }
        }
    }
}

// ---------------------------------------------------------------------------

static const int SMEM_NODE = 32 * FDIM * 4;

extern "C" void kernel_launch(void* const* d_in, const int* in_sizes, int n_in,
                              void* d_out, int out_size)
{
    const float* x    = (const float*)d_in[0];
    const void*  eidx = d_in[1];
    const float* ew   = (const float*)d_in[2];
    const float* ea   = (const float*)d_in[3];
    const float* w1   = (const float*)d_in[4];
    const float* b1   = (const float*)d_in[5];
    const float* w2   = (const float*)d_in[6];
    const float* b2   = (const float*)d_in[7];
    const float* l1   = (const float*)d_in[8];
    const float* l2   = (const float*)d_in[9];
    const float* l2b  = (const float*)d_in[10];

    const int N = in_sizes[0] / FDIM;     // x is [N,256]
    const int E = in_sizes[1] / 2;        // edge_index is [2,E]

    cudaFuncSetAttribute(edge_kernel, cudaFuncAttributeMaxDynamicSharedMemorySize, SMEM_EDGE);
    cudaFuncSetAttribute(node_gemm,   cudaFuncAttributeMaxDynamicSharedMemorySize, SMEM_NODE);

    int count64 = E / 2 < 32 ? E / 2 : 32;
    detect_idx_kernel<<<1, 32>>>((const long long*)eidx, count64, N);          // 0
    convert_idx_kernel<<<(E + 255) / 256, 256>>>(eidx, E, N);                  // 1

    const int total4 = (N * FDIM) / 4;
    zero_agg_kernel<<<(total4 + 255) / 256, 256>>>(total4);                    // 2

    prep_w2t<<<256, 256>>>(w2);                                                // 3

    // xs = x @ lin1_w  -> g_xs
    node_gemm<<<(N + 31) / 32, 256, SMEM_NODE>>>(x, l1, nullptr, nullptr,      // 4
                                                 nullptr, N, 0);

    warm_kernel<<<128, 256>>>(32768);                                          // 5

    // fused edge MLP (stage A scalar, stage B mma.sync) + scatter-add
    edge_kernel<<<(E + EDG - 1) / EDG, 256, SMEM_EDGE>>>(ew, ea, w1, b1, b2, E); // 6

    // out = x + ssp(agg @ lin2_w + lin2_b)
    node_gemm<<<(N + 31) / 32, 256, SMEM_NODE>>>(nullptr, l2, l2b, x,          // 7
                                                 (float*)d_out, N, 1);
}

// round 14
// speedup vs baseline: 2.5488x; 1.6649x over previous
#include <cuda_runtime.h>
#include <cuda_fp16.h>
#include <cstdint>

// ---------------------------------------------------------------------------
// InteractionBlock (SchNet CFConv).  R14:
//  - edge culling: ~26% of edges have cutoff C=0 -> compacted out before MLP
//  - fp16 2-term split (A=hid hi+lo fp16, B=w2 single fp16): 2 mma terms
//    instead of bf16x3's 3, half the B smem traffic, k=32 chunks, B frags
//    shared across terms. 2 CTAs/SM @ 82KB smem.
// ---------------------------------------------------------------------------

#define FDIM 256
#define GDIM 50

#define NMAX 10240
#define EMAX 330000
__device__ __align__(16) float g_xs[NMAX * FDIM];
__device__ __align__(16) float g_agg[NMAX * FDIM];
__device__ int   g_si[EMAX];
__device__ int   g_sj[EMAX];
__device__ float g_C[EMAX];
__device__ int   g_eid[EMAX];
__device__ int   g_ecount;
__device__ int   g_idx64;
// w2 transposed fp16: [kc 8][n 256][kk 32]
__device__ __align__(16) __half g_w2t[8 * 256 * 32];

typedef unsigned long long u64;

// ---- packed f32x2 helpers --------------------------------------------------
__device__ __forceinline__ u64 pack2(float lo, float hi) {
    u64 r; asm("mov.b64 %0, {%1, %2};" : "=l"(r) : "f"(lo), "f"(hi)); return r;
}
__device__ __forceinline__ void unpack2(u64 v, float& lo, float& hi) {
    asm("mov.b64 {%0, %1}, %2;" : "=f"(lo), "=f"(hi) : "l"(v));
}
__device__ __forceinline__ u64 ffma2(u64 a, u64 b, u64 c) {
    u64 d; asm("fma.rn.f32x2 %0, %1, %2, %3;" : "=l"(d) : "l"(a), "l"(b), "l"(c)); return d;
}
// fast shifted softplus (MUFU; ~1e-7 abs err)
__device__ __forceinline__ float sspf(float v) {
    float t = __expf(-fabsf(v));
    return fmaxf(v, 0.f) + __logf(1.f + t) - 0.69314718055994530942f;
}

// ---- base-ISA tensor core mma (fp16 in, fp32 accum) ------------------------
__device__ __forceinline__ void mma16816(float* d,
    uint32_t a0, uint32_t a1, uint32_t a2, uint32_t a3,
    uint32_t b0, uint32_t b1)
{
    asm volatile(
        "mma.sync.aligned.m16n8k16.row.col.f32.f16.f16.f32 "
        "{%0,%1,%2,%3}, {%4,%5,%6,%7}, {%8,%9}, {%0,%1,%2,%3};"
        : "+f"(d[0]), "+f"(d[1]), "+f"(d[2]), "+f"(d[3])
        : "r"(a0), "r"(a1), "r"(a2), "r"(a3), "r"(b0), "r"(b1));
}

// ---- cp.async --------------------------------------------------------------
__device__ __forceinline__ void cp16(uint32_t smem_dst, const void* gsrc) {
    asm volatile("cp.async.cg.shared.global [%0], [%1], 16;"
                 :: "r"(smem_dst), "l"(gsrc) : "memory");
}
__device__ __forceinline__ void cp_commit() {
    asm volatile("cp.async.commit_group;" ::: "memory");
}
template <int N> __device__ __forceinline__ void cp_wait() {
    asm volatile("cp.async.wait_group %0;" :: "n"(N) : "memory");
}
__device__ __forceinline__ uint32_t smem_u32(const void* p) {
    uint32_t a;
    asm("{ .reg .u64 t; cvta.to.shared.u64 t, %1; cvt.u32.u64 %0, t; }"
        : "=r"(a) : "l"(p));
    return a;
}

// ---------------------------------------------------------------------------
extern "C" __global__ void detect_idx_kernel(const long long* __restrict__ p,
                                             int count64, int N)
{
    int lane = threadIdx.x;
    int ok = 1;
    if (lane < count64) {
        long long v = p[lane];
        ok = (v >= 0 && v < (long long)N) ? 1 : 0;
    }
    unsigned all = __ballot_sync(0xFFFFFFFFu, ok);
    if (lane == 0) { g_idx64 = (all == 0xFFFFFFFFu) ? 1 : 0; g_ecount = 0; }
}

// cull C=0 edges; compact survivors (si, sj, C, original id)
extern "C" __global__ void cull_kernel(const void* __restrict__ p,
                                       const float* __restrict__ ew,
                                       int E, int N)
{
    int e = blockIdx.x * blockDim.x + threadIdx.x;
    if (e >= E) return;
    float a = ew[e*3+0], b = ew[e*3+1], c2 = ew[e*3+2];
    float d = sqrtf(a*a + b*b + c2*c2);
    if (d > 2.0f) return;
    float C = 0.5f * (__cosf(d * 1.57079632679489662f) + 1.f);
    int iv, jv;
    if (g_idx64) {
        const long long* q = (const long long*)p;
        iv = (int)q[e]; jv = (int)q[E + e];
    } else {
        const int* q = (const int*)p;
        iv = q[e]; jv = q[E + e];
    }
    int pos = atomicAdd(&g_ecount, 1);
    g_si[pos]  = min(max(iv, 0), N - 1);
    g_sj[pos]  = min(max(jv, 0), N - 1);
    g_C[pos]   = C;
    g_eid[pos] = e;
}

// transpose w2 -> fp16, [kc 8][n 256][kk 32]
extern "C" __global__ void prep_w2t(const float* __restrict__ w2) {
    int idx = blockIdx.x * 256 + threadIdx.x;    // 65536
    int k = idx >> 8, n = idx & 255;
    float v = w2[k * 256 + n];
    g_w2t[(k >> 5) * (256 * 32) + n * 32 + (k & 31)] = __float2half_rn(v);
}

extern "C" __global__ void warm_kernel(int n) {
    int i = blockIdx.x * blockDim.x + threadIdx.x;
    if (i < n) {
        unsigned a = ((const unsigned*)g_w2t)[i];
        if (blockIdx.x == 0x7FFFFFF0) g_agg[0] = (float)a;   // never
    }
}

extern "C" __global__ void zero_agg_kernel(int total4) {
    int i = blockIdx.x * blockDim.x + threadIdx.x;
    if (i < total4) {
        float4 z; z.x = 0.f; z.y = 0.f; z.z = 0.f; z.w = 0.f;
        reinterpret_cast<float4*>(g_agg)[i] = z;
    }
}

// ---------------------------------------------------------------------------
// Fused edge kernel: 32 compacted edges/CTA, 256 threads, 2 CTAs/SM.
// smem (bytes):
//   HID_HI [0,16896)        32 rows x 264 fp16 (stride 528 B)
//   HID_LO [16896,33792)
//   BBUF   [33792,74752)    2 bufs x 20480 B; B row stride 80 B (k=32 chunk)
//   EA_S   [74752,81920)    32x56 fp32
//   SC/SI/SJ aux -> total 82304
// ---------------------------------------------------------------------------
#define EDG      32
#define HID_STRB 528
#define HID_HI   0
#define HID_LO   16896
#define BBUF     33792
#define B_STRB   80
#define BUF_SZ   20480
#define EA_S     74752
#define SC_OFF   81920
#define SI_OFF   82048
#define SJ_OFF   82176
#define SMEM_EDGE 82304

// one B chunk = 256 rows x 64 B fp16 (stride 80): 1024 cp16
__device__ __forceinline__ void load_b_chunk(uint32_t sbase, int buf, int cc, int tid)
{
    uint32_t dbase = sbase + BBUF + buf * BUF_SZ;
    const char* src = (const char*)g_w2t + cc * 16384;
    #pragma unroll
    for (int q = 0; q < 4; ++q) {
        int t = q * 256 + tid;               // [0,1024)
        int row = t >> 2, seg = t & 3;
        cp16(dbase + row * B_STRB + seg * 16, src + row * 64 + seg * 16);
    }
}

extern "C" __global__ void __launch_bounds__(256, 2)
edge_kernel(const float* __restrict__ ea,
            const float* __restrict__ w1,
            const float* __restrict__ b1,
            const float* __restrict__ b2)
{
    const int EC = g_ecount;                 // compacted edge count
    const int e0 = blockIdx.x * EDG;
    if (e0 >= EC) return;

    extern __shared__ char smem_raw[];
    const uint32_t sbase = smem_u32(smem_raw);
    const int tid = threadIdx.x;

    float* ea_s = (float*)(smem_raw + EA_S);
    float* sC   = (float*)(smem_raw + SC_OFF);
    int*   si   = (int*)(smem_raw + SI_OFF);
    int*   sj   = (int*)(smem_raw + SJ_OFF);

    if (tid < EDG) {
        int e = e0 + tid;
        float C = 0.f; int iv = 0, jv = 0;
        if (e < EC) { iv = g_si[e]; jv = g_sj[e]; C = g_C[e]; }
        si[tid] = iv; sj[tid] = jv; sC[tid] = C;
    }

    // gather edge_attr rows of surviving edges: [32][56] fp32, zero-padded
    for (int idx = tid; idx < EDG * 56; idx += 256) {
        int r = idx / 56, k = idx % 56;
        float v = 0.f;
        int e = e0 + r;
        if (k < GDIM && e < EC) v = ea[(size_t)g_eid[e] * GDIM + k];
        ea_s[idx] = v;
    }

    // prefetch B chunks 0,1 (overlaps stage A)
    load_b_chunk(sbase, 0, 0, tid); cp_commit();
    load_b_chunk(sbase, 1, 1, tid); cp_commit();
    __syncthreads();

    // ---------------- Stage A (scalar f32x2): hid = ssp(ea@W1+b1) ----------
    {
        const int c = tid;
        u64 wp[26];
        #pragma unroll
        for (int kc = 0; kc < 13; ++kc) {
            float w0 = (4*kc+0 < GDIM) ? w1[(4*kc+0)*FDIM + c] : 0.f;
            float wv1 = (4*kc+1 < GDIM) ? w1[(4*kc+1)*FDIM + c] : 0.f;
            float w2v = (4*kc+2 < GDIM) ? w1[(4*kc+2)*FDIM + c] : 0.f;
            float w3 = (4*kc+3 < GDIM) ? w1[(4*kc+3)*FDIM + c] : 0.f;
            wp[2*kc]   = pack2(w0, wv1);
            wp[2*kc+1] = pack2(w2v, w3);
        }
        const float b1c = b1[c];
        #pragma unroll 1
        for (int ch = 0; ch < 2; ++ch) {
            u64 acc[16];
            #pragma unroll
            for (int e = 0; e < 16; ++e) acc[e] = 0ULL;
            #pragma unroll
            for (int kc = 0; kc < 13; ++kc) {
                const float* base = ea_s + (ch * 16) * 56 + kc * 4;
                #pragma unroll
                for (int e = 0; e < 16; ++e) {
                    ulonglong2 v = *reinterpret_cast<const ulonglong2*>(base + e * 56);
                    acc[e] = ffma2(v.x, wp[2*kc],   acc[e]);
                    acc[e] = ffma2(v.y, wp[2*kc+1], acc[e]);
                }
            }
            #pragma unroll
            for (int e = 0; e < 16; ++e) {
                float lo, hi; unpack2(acc[e], lo, hi);
                float v = sspf(lo + hi + b1c);
                __half vh = __float2half_rn(v);
                __half vl = __float2half_rn(v - __half2float(vh));   // exact
                int row = ch * 16 + e;
                *(__half*)(smem_raw + HID_HI + row * HID_STRB + tid * 2) = vh;
                *(__half*)(smem_raw + HID_LO + row * HID_STRB + tid * 2) = vl;
            }
        }
    }
    __syncthreads();   // hid ready

    // ---------------- Stage B: mma.sync fp16 2-term, D in registers --------
    const int lane = tid & 31;
    const int w    = tid >> 5;          // warp owns cols [w*32, w*32+32)
    const int lp   = lane & 3;
    const int lg   = lane >> 2;

    float acc[2][4][4];                 // [m-tile][n-tile][frag]
    #pragma unroll
    for (int m = 0; m < 2; ++m)
        #pragma unroll
        for (int t = 0; t < 4; ++t)
            #pragma unroll
            for (int q = 0; q < 4; ++q) acc[m][t][q] = 0.f;

    #pragma unroll 1
    for (int kc = 0; kc < 8; ++kc) {    // 32 k per chunk
        if (kc == 7) cp_wait<0>(); else cp_wait<1>();
        __syncthreads();                // chunk kc visible

        const char* Bbase = smem_raw + BBUF + (kc & 1) * BUF_SZ;
        #pragma unroll
        for (int ks = 0; ks < 2; ++ks) {
            // B fragments loaded once, shared by both terms
            uint32_t bfr[4][2];
            #pragma unroll
            for (int t = 0; t < 4; ++t) {
                const char* bp = Bbase + (w*32 + t*8 + lg) * B_STRB + ks*32 + lp*4;
                bfr[t][0] = *(const uint32_t*)bp;
                bfr[t][1] = *(const uint32_t*)(bp + 16);
            }
            #pragma unroll
            for (int term = 0; term < 2; ++term) {
                const char* Ab = smem_raw + (term ? HID_LO : HID_HI);
                #pragma unroll
                for (int m = 0; m < 2; ++m) {
                    const char* ap = Ab + (m*16 + lg) * HID_STRB + kc*64 + ks*32 + lp*4;
                    uint32_t a0 = *(const uint32_t*)ap;
                    uint32_t a1 = *(const uint32_t*)(ap + 8 * HID_STRB);
                    uint32_t a2 = *(const uint32_t*)(ap + 16);
                    uint32_t a3 = *(const uint32_t*)(ap + 8 * HID_STRB + 16);
                    #pragma unroll
                    for (int t = 0; t < 4; ++t)
                        mma16816(acc[m][t], a0, a1, a2, a3, bfr[t][0], bfr[t][1]);
                }
            }
        }
        __syncthreads();                // done with buf[kc&1]
        if (kc + 2 < 8) {
            load_b_chunk(sbase, kc & 1, kc + 2, tid);
            cp_commit();
        }
    }

    // ---------------- epilogue: (D+b2)*C*xs[j] -> atomicAdd agg[i] ---------
    float b2a[4], b2b[4];
    #pragma unroll
    for (int t = 0; t < 4; ++t) {
        int c0 = w*32 + t*8 + 2*lp;
        b2a[t] = b2[c0];
        b2b[t] = b2[c0 + 1];
    }
    #pragma unroll
    for (int m = 0; m < 2; ++m) {
        #pragma unroll
        for (int half = 0; half < 2; ++half) {
            int e = m*16 + lg + half*8;
            float Ce = sC[e];
            if (Ce != 0.f) {
                int ii = si[e], jj = sj[e];
                const float* xr = g_xs + (size_t)jj * FDIM;
                float*       ar = g_agg + (size_t)ii * FDIM;
                #pragma unroll
                for (int t = 0; t < 4; ++t) {
                    int c0 = w*32 + t*8 + 2*lp;
                    float2 xv = *(const float2*)(xr + c0);
                    float d0 = acc[m][t][half*2 + 0];
                    float d1 = acc[m][t][half*2 + 1];
                    atomicAdd(&ar[c0],     (d0 + b2a[t]) * Ce * xv.x);
                    atomicAdd(&ar[c0 + 1], (d1 + b2b[t]) * Ce * xv.y);
                }
            }
        }
    }
}

// ---------------------------------------------------------------------------
// Node GEMM (scalar f32x2). mode 0: g_xs = in @ w.
// mode 1: out = xres + ssp(g_agg @ w + bias).
// ---------------------------------------------------------------------------
extern "C" __global__ void __launch_bounds__(256, 3)
node_gemm(const float* __restrict__ in,
          const float* __restrict__ w,
          const float* __restrict__ bias,
          const float* __restrict__ xres,
          float* __restrict__ out,
          int N, int mode)
{
    extern __shared__ float tile[];          // 32*256 floats
    const int tid = threadIdx.x;
    const int n0  = blockIdx.x * 32;

    const float* src = (mode == 0) ? in : (const float*)g_agg;
    float* dst       = (mode == 0) ? g_xs : out;

    {
        const float4* s4 = reinterpret_cast<const float4*>(src);
        float4* t4 = reinterpret_cast<float4*>(tile);
        #pragma unroll
        for (int q = 0; q < 8; ++q) {
            int idx = q * 256 + tid;
            int r = idx >> 6;
            float4 v = make_float4(0.f, 0.f, 0.f, 0.f);
            if (n0 + r < N) v = s4[(size_t)(n0 + r) * 64 + (idx & 63)];
            t4[idx] = v;
        }
    }
    __syncthreads();

    const int c = tid;
    #pragma unroll 1
    for (int ch = 0; ch < 2; ++ch) {
        u64 acc[16];
        #pragma unroll
        for (int r = 0; r < 16; ++r) acc[r] = 0ULL;

        float a0 = w[0*FDIM + c], a1 = w[1*FDIM + c];
        float a2 = w[2*FDIM + c], a3 = w[3*FDIM + c];
        float p0 = w[4*FDIM + c], p1 = w[5*FDIM + c];
        float p2 = w[6*FDIM + c], p3 = w[7*FDIM + c];
        #pragma unroll 1
        for (int kc = 0; kc < 64; ++kc) {
            u64 wp0 = pack2(a0, a1);
            u64 wp1 = pack2(a2, a3);
            a0 = p0; a1 = p1; a2 = p2; a3 = p3;
            if (kc + 2 < 64) {
                int k0 = (kc + 2) * 4;
                p0 = w[(k0+0)*FDIM + c]; p1 = w[(k0+1)*FDIM + c];
                p2 = w[(k0+2)*FDIM + c]; p3 = w[(k0+3)*FDIM + c];
            }
            const float* base = tile + (ch * 16) * FDIM + kc * 4;
            #pragma unroll
            for (int r = 0; r < 16; ++r) {
                ulonglong2 v = *reinterpret_cast<const ulonglong2*>(base + r*FDIM);
                acc[r] = ffma2(v.x, wp0, acc[r]);
                acc[r] = ffma2(v.y, wp1, acc[r]);
            }
        }
        #pragma unroll
        for (int r = 0; r < 16; ++r) {
            int n = n0 + ch * 16 + r;
            if (n < N) {
                float lo, hi; unpack2(acc[r], lo, hi);
                float val = lo + hi;
                if (mode == 0) dst[n * FDIM + c] = val;
                else dst[n * FDIM + c] = xres[n * FDIM + c] + sspf(val + bias[c]);
            }
        }
    }
}

// ---------------------------------------------------------------------------

static const int SMEM_NODE = 32 * FDIM * 4;

extern "C" void kernel_launch(void* const* d_in, const int* in_sizes, int n_in,
                              void* d_out, int out_size)
{
    const float* x    = (const float*)d_in[0];
    const void*  eidx = d_in[1];
    const float* ew   = (const float*)d_in[2];
    const float* ea   = (const float*)d_in[3];
    const float* w1   = (const float*)d_in[4];
    const float* b1   = (const float*)d_in[5];
    const float* w2   = (const float*)d_in[6];
    const float* b2   = (const float*)d_in[7];
    const float* l1   = (const float*)d_in[8];
    const float* l2   = (const float*)d_in[9];
    const float* l2b  = (const float*)d_in[10];

    const int N = in_sizes[0] / FDIM;     // x is [N,256]
    const int E = in_sizes[1] / 2;        // edge_index is [2,E]

    cudaFuncSetAttribute(edge_kernel, cudaFuncAttributeMaxDynamicSharedMemorySize, SMEM_EDGE);
    cudaFuncSetAttribute(node_gemm,   cudaFuncAttributeMaxDynamicSharedMemorySize, SMEM_NODE);

    int count64 = E / 2 < 32 ? E / 2 : 32;
    detect_idx_kernel<<<1, 32>>>((const long long*)eidx, count64, N);          // also zeroes g_ecount
    cull_kernel<<<(E + 255) / 256, 256>>>(eidx, ew, E, N);

    const int total4 = (N * FDIM) / 4;
    zero_agg_kernel<<<(total4 + 255) / 256, 256>>>(total4);

    prep_w2t<<<256, 256>>>(w2);

    // xs = x @ lin1_w  -> g_xs
    node_gemm<<<(N + 31) / 32, 256, SMEM_NODE>>>(x, l1, nullptr, nullptr,
                                                 nullptr, N, 0);

    warm_kernel<<<64, 256>>>(16384);

    // fused edge MLP (stage A scalar, stage B fp16 mma) + scatter-add
    edge_kernel<<<(E + EDG - 1) / EDG, 256, SMEM_EDGE>>>(ea, w1, b1, b2);

    // out = x + ssp(agg @ lin2_w + lin2_b)
    node_gemm<<<(N + 31) / 32, 256, SMEM_NODE>>>(nullptr, l2, l2b, x,
                                                 (float*)d_out, N, 1);
}

// round 16
// speedup vs baseline: 3.3292x; 1.3062x over previous
#include <cuda_runtime.h>
#include <cuda_fp16.h>
#include <cstdint>

// ---------------------------------------------------------------------------
// InteractionBlock (SchNet CFConv).  R16 = R15 with the smem-stride bug fixed:
// stage A (layer-1 MLP) uses the SAME chunked [n][32-k] stride-80 format and
// the SAME BBUF double-buffer pipeline as stage B (w1 chunks first, then w2).
// Edge culling + fp16 2-term split + red.add.v2 epilogue.  2 CTAs/SM @ 85KB.
// ---------------------------------------------------------------------------

#define FDIM 256
#define GDIM 50

#define NMAX 10240
#define EMAX 330000
__device__ __align__(16) float g_xs[NMAX * FDIM];
__device__ __align__(16) float g_agg[NMAX * FDIM];
__device__ int   g_si[EMAX];
__device__ int   g_sj[EMAX];
__device__ float g_C[EMAX];
__device__ int   g_eid[EMAX];
__device__ int   g_ecount;
__device__ int   g_idx64;
// w2 transposed fp16: [kc 8][n 256][kk 32]
__device__ __align__(16) __half g_w2t[8 * 256 * 32];
// w1 transposed fp16: [kc 2][n 256][kk 32] (k>=50 zero)
__device__ __align__(16) __half g_w1t[2 * 256 * 32];

typedef unsigned long long u64;

__device__ __forceinline__ float sspf(float v) {
    float t = __expf(-fabsf(v));
    return fmaxf(v, 0.f) + __logf(1.f + t) - 0.69314718055994530942f;
}

// ---- base-ISA tensor core mma (fp16 in, fp32 accum) ------------------------
__device__ __forceinline__ void mma16816(float* d,
    uint32_t a0, uint32_t a1, uint32_t a2, uint32_t a3,
    uint32_t b0, uint32_t b1)
{
    asm volatile(
        "mma.sync.aligned.m16n8k16.row.col.f32.f16.f16.f32 "
        "{%0,%1,%2,%3}, {%4,%5,%6,%7}, {%8,%9}, {%0,%1,%2,%3};"
        : "+f"(d[0]), "+f"(d[1]), "+f"(d[2]), "+f"(d[3])
        : "r"(a0), "r"(a1), "r"(a2), "r"(a3), "r"(b0), "r"(b1));
}

// ---- cp.async / misc -------------------------------------------------------
__device__ __forceinline__ void cp16(uint32_t smem_dst, const void* gsrc) {
    asm volatile("cp.async.cg.shared.global [%0], [%1], 16;"
                 :: "r"(smem_dst), "l"(gsrc) : "memory");
}
__device__ __forceinline__ void cp_commit() {
    asm volatile("cp.async.commit_group;" ::: "memory");
}
template <int N> __device__ __forceinline__ void cp_wait() {
    asm volatile("cp.async.wait_group %0;" :: "n"(N) : "memory");
}
__device__ __forceinline__ uint32_t smem_u32(const void* p) {
    uint32_t a;
    asm("{ .reg .u64 t; cvta.to.shared.u64 t, %1; cvt.u32.u64 %0, t; }"
        : "=r"(a) : "l"(p));
    return a;
}
__device__ __forceinline__ void red_add_v2(float* ptr, float x, float y) {
    asm volatile("red.global.add.v2.f32 [%0], {%1, %2};"
                 :: "l"(ptr), "f"(x), "f"(y) : "memory");
}

// ---------------------------------------------------------------------------
extern "C" __global__ void detect_idx_kernel(const long long* __restrict__ p,
                                             int count64, int N)
{
    int lane = threadIdx.x;
    int ok = 1;
    if (lane < count64) {
        long long v = p[lane];
        ok = (v >= 0 && v < (long long)N) ? 1 : 0;
    }
    unsigned all = __ballot_sync(0xFFFFFFFFu, ok);
    if (lane == 0) { g_idx64 = (all == 0xFFFFFFFFu) ? 1 : 0; g_ecount = 0; }
}

// cull C=0 edges; compact survivors
extern "C" __global__ void cull_kernel(const void* __restrict__ p,
                                       const float* __restrict__ ew,
                                       int E, int N)
{
    int e = blockIdx.x * blockDim.x + threadIdx.x;
    if (e >= E) return;
    float a = ew[e*3+0], b = ew[e*3+1], c2 = ew[e*3+2];
    float d = sqrtf(a*a + b*b + c2*c2);
    if (d > 2.0f) return;
    float C = 0.5f * (__cosf(d * 1.57079632679489662f) + 1.f);
    int iv, jv;
    if (g_idx64) {
        const long long* q = (const long long*)p;
        iv = (int)q[e]; jv = (int)q[E + e];
    } else {
        const int* q = (const int*)p;
        iv = q[e]; jv = q[E + e];
    }
    int pos = atomicAdd(&g_ecount, 1);
    g_si[pos]  = min(max(iv, 0), N - 1);
    g_sj[pos]  = min(max(jv, 0), N - 1);
    g_C[pos]   = C;
    g_eid[pos] = e;
}

// transpose w2 -> fp16, [kc 8][n 256][kk 32]
extern "C" __global__ void prep_w2t(const float* __restrict__ w2) {
    int idx = blockIdx.x * 256 + threadIdx.x;    // 65536
    int k = idx >> 8, n = idx & 255;
    g_w2t[(k >> 5) * (256 * 32) + n * 32 + (k & 31)] =
        __float2half_rn(w2[k * 256 + n]);
}

// transpose w1 -> fp16, [kc 2][n 256][kk 32] zero-padded (k>=50)
extern "C" __global__ void prep_w1t(const float* __restrict__ w1) {
    int idx = blockIdx.x * 256 + threadIdx.x;    // 16384
    int n = idx >> 6, k = idx & 63;
    g_w1t[(k >> 5) * (256 * 32) + n * 32 + (k & 31)] =
        __float2half_rn(k < GDIM ? w1[k * FDIM + n] : 0.f);
}

extern "C" __global__ void warm_kernel(int n) {
    int i = blockIdx.x * blockDim.x + threadIdx.x;
    if (i < n) {
        unsigned a = ((const unsigned*)g_w2t)[i];
        unsigned b = ((const unsigned*)g_w1t)[i & 8191];
        if (blockIdx.x == 0x7FFFFFF0) g_agg[0] = (float)(a + b);   // never
    }
}

extern "C" __global__ void zero_agg_kernel(int total4) {
    int i = blockIdx.x * blockDim.x + threadIdx.x;
    if (i < total4) {
        float4 z; z.x = 0.f; z.y = 0.f; z.z = 0.f; z.w = 0.f;
        reinterpret_cast<float4*>(g_agg)[i] = z;
    }
}

// ---------------------------------------------------------------------------
// Fused edge kernel: 32 compacted edges/CTA, 256 threads, 2 CTAs/SM.
// smem (bytes):
//   HID_HI [0,16896)        32 rows x 264 fp16 (stride 528)
//   HID_LO [16896,33792)
//   BBUF   [33792,74752)    2 x 20480; chunk [256 n][32 k] stride 80
//   EA_HI  [74752,79872)    2 chunks x [32 r][32 k] stride 80 (2560 each)
//   EA_LO  [79872,84992)
//   aux -> total 85376
// ---------------------------------------------------------------------------
#define EDG      32
#define HID_STRB 528
#define HID_HI   0
#define HID_LO   16896
#define BBUF     33792
#define B_STRB   80
#define BUF_SZ   20480
#define EA_HI    74752
#define EA_LO    79872
#define EA_CHK   2560
#define SC_OFF   84992
#define SI_OFF   85120
#define SJ_OFF   85248
#define SMEM_EDGE 85376

// one chunk = 256 rows x 64 B fp16 (smem stride 80): 1024 cp16
__device__ __forceinline__ void load_chunk(uint32_t sbase, int buf,
                                           const __half* gchunk, int tid)
{
    uint32_t dbase = sbase + BBUF + buf * BUF_SZ;
    const char* src = (const char*)gchunk;
    #pragma unroll
    for (int q = 0; q < 4; ++q) {
        int t = q * 256 + tid;
        int row = t >> 2, seg = t & 3;
        cp16(dbase + row * B_STRB + seg * 16, src + row * 64 + seg * 16);
    }
}

extern "C" __global__ void __launch_bounds__(256, 2)
edge_kernel(const float* __restrict__ ea,
            const float* __restrict__ b1,
            const float* __restrict__ b2)
{
    const int EC = g_ecount;
    const int e0 = blockIdx.x * EDG;
    if (e0 >= EC) return;

    extern __shared__ char smem_raw[];
    const uint32_t sbase = smem_u32(smem_raw);
    const int tid = threadIdx.x;

    float* sC = (float*)(smem_raw + SC_OFF);
    int*   si = (int*)(smem_raw + SI_OFF);
    int*   sj = (int*)(smem_raw + SJ_OFF);

    if (tid < EDG) {
        int e = e0 + tid;
        float C = 0.f; int iv = 0, jv = 0;
        if (e < EC) { iv = g_si[e]; jv = g_sj[e]; C = g_C[e]; }
        si[tid] = iv; sj[tid] = jv; sC[tid] = C;
    }

    // gather + fp16-split edge_attr into chunked EA slabs, zero-padded
    #pragma unroll
    for (int q = 0; q < 8; ++q) {
        int idx = q * 256 + tid;            // [0, 2048)
        int r = idx >> 6, k = idx & 63;
        float v = 0.f;
        int e = e0 + r;
        if (k < GDIM && e < EC) v = ea[(size_t)g_eid[e] * GDIM + k];
        __half vh = __float2half_rn(v);
        __half vl = __float2half_rn(v - __half2float(vh));
        int off = (k >> 5) * EA_CHK + r * B_STRB + (k & 31) * 2;
        *(__half*)(smem_raw + EA_HI + off) = vh;
        *(__half*)(smem_raw + EA_LO + off) = vl;
    }

    // pipeline prologue: w1 chunks 0,1 into the two buffers
    load_chunk(sbase, 0, g_w1t,        tid); cp_commit();
    load_chunk(sbase, 1, g_w1t + 8192, tid); cp_commit();

    const int lane = tid & 31;
    const int w    = tid >> 5;          // warp owns cols [w*32, w*32+32)
    const int lp   = lane & 3;
    const int lg   = lane >> 2;

    // ---------------- Stage A (mma fp16 2-term): hid = ssp(ea@W1+b1) -------
    {
        float accA[2][4][4];
        #pragma unroll
        for (int m = 0; m < 2; ++m)
            #pragma unroll
            for (int t = 0; t < 4; ++t)
                #pragma unroll
                for (int q = 0; q < 4; ++q) accA[m][t][q] = 0.f;

        #pragma unroll 1
        for (int kc = 0; kc < 2; ++kc) {
            cp_wait<1>();
            __syncthreads();            // w1 chunk kc + EA stores visible

            const char* Bbase = smem_raw + BBUF + (kc & 1) * BUF_SZ;
            #pragma unroll
            for (int ks = 0; ks < 2; ++ks) {
                uint32_t bfr[4][2];
                #pragma unroll
                for (int t = 0; t < 4; ++t) {
                    const char* bp = Bbase + (w*32 + t*8 + lg) * B_STRB + ks*32 + lp*4;
                    bfr[t][0] = *(const uint32_t*)bp;
                    bfr[t][1] = *(const uint32_t*)(bp + 16);
                }
                #pragma unroll
                for (int term = 0; term < 2; ++term) {
                    const char* Ab = smem_raw + (term ? EA_LO : EA_HI) + kc * EA_CHK;
                    #pragma unroll
                    for (int m = 0; m < 2; ++m) {
                        const char* ap = Ab + (m*16 + lg) * B_STRB + ks*32 + lp*4;
                        uint32_t a0 = *(const uint32_t*)ap;
                        uint32_t a1 = *(const uint32_t*)(ap + 8 * B_STRB);
                        uint32_t a2 = *(const uint32_t*)(ap + 16);
                        uint32_t a3 = *(const uint32_t*)(ap + 8 * B_STRB + 16);
                        #pragma unroll
                        for (int t = 0; t < 4; ++t)
                            mma16816(accA[m][t], a0, a1, a2, a3, bfr[t][0], bfr[t][1]);
                    }
                }
            }
            __syncthreads();            // done with buf kc
            // refill this buffer with w2 chunk kc
            load_chunk(sbase, kc, g_w2t + kc * 8192, tid);
            cp_commit();
        }

        // ssp + b1, split fp16, store hid
        float b1a[4], b1b[4];
        #pragma unroll
        for (int t = 0; t < 4; ++t) {
            int c0 = w*32 + t*8 + 2*lp;
            b1a[t] = b1[c0]; b1b[t] = b1[c0 + 1];
        }
        #pragma unroll
        for (int m = 0; m < 2; ++m) {
            #pragma unroll
            for (int half = 0; half < 2; ++half) {
                int row = m*16 + lg + half*8;
                #pragma unroll
                for (int t = 0; t < 4; ++t) {
                    int c0 = w*32 + t*8 + 2*lp;
                    float v0 = sspf(accA[m][t][half*2 + 0] + b1a[t]);
                    float v1 = sspf(accA[m][t][half*2 + 1] + b1b[t]);
                    __half h0 = __float2half_rn(v0);
                    __half h1 = __float2half_rn(v1);
                    __half l0 = __float2half_rn(v0 - __half2float(h0));
                    __half l1 = __float2half_rn(v1 - __half2float(h1));
                    uint32_t hp  = ((uint32_t)__half_as_ushort(h1) << 16) | __half_as_ushort(h0);
                    uint32_t lpk = ((uint32_t)__half_as_ushort(l1) << 16) | __half_as_ushort(l0);
                    *(uint32_t*)(smem_raw + HID_HI + row * HID_STRB + c0 * 2) = hp;
                    *(uint32_t*)(smem_raw + HID_LO + row * HID_STRB + c0 * 2) = lpk;
                }
            }
        }
    }

    // ---------------- Stage B (mma fp16 2-term): W = hid @ w2 --------------
    float acc[2][4][4];
    #pragma unroll
    for (int m = 0; m < 2; ++m)
        #pragma unroll
        for (int t = 0; t < 4; ++t)
            #pragma unroll
            for (int q = 0; q < 4; ++q) acc[m][t][q] = 0.f;

    #pragma unroll 1
    for (int kc = 0; kc < 8; ++kc) {
        if (kc == 7) cp_wait<0>(); else cp_wait<1>();
        __syncthreads();                // w2 chunk kc + hid stores visible

        const char* Bbase = smem_raw + BBUF + (kc & 1) * BUF_SZ;
        #pragma unroll
        for (int ks = 0; ks < 2; ++ks) {
            uint32_t bfr[4][2];
            #pragma unroll
            for (int t = 0; t < 4; ++t) {
                const char* bp = Bbase + (w*32 + t*8 + lg) * B_STRB + ks*32 + lp*4;
                bfr[t][0] = *(const uint32_t*)bp;
                bfr[t][1] = *(const uint32_t*)(bp + 16);
            }
            #pragma unroll
            for (int term = 0; term < 2; ++term) {
                const char* Ab = smem_raw + (term ? HID_LO : HID_HI);
                #pragma unroll
                for (int m = 0; m < 2; ++m) {
                    const char* ap = Ab + (m*16 + lg) * HID_STRB + kc*64 + ks*32 + lp*4;
                    uint32_t a0 = *(const uint32_t*)ap;
                    uint32_t a1 = *(const uint32_t*)(ap + 8 * HID_STRB);
                    uint32_t a2 = *(const uint32_t*)(ap + 16);
                    uint32_t a3 = *(const uint32_t*)(ap + 8 * HID_STRB + 16);
                    #pragma unroll
                    for (int t = 0; t < 4; ++t)
                        mma16816(acc[m][t], a0, a1, a2, a3, bfr[t][0], bfr[t][1]);
                }
            }
        }
        __syncthreads();
        if (kc + 2 < 8) {
            load_chunk(sbase, kc & 1, g_w2t + (kc + 2) * 8192, tid);
            cp_commit();
        }
    }

    // ---------------- epilogue: (D+b2)*C*xs[j] -> red.v2 agg[i] ------------
    float b2a[4], b2b[4];
    #pragma unroll
    for (int t = 0; t < 4; ++t) {
        int c0 = w*32 + t*8 + 2*lp;
        b2a[t] = b2[c0];
        b2b[t] = b2[c0 + 1];
    }
    #pragma unroll
    for (int m = 0; m < 2; ++m) {
        #pragma unroll
        for (int half = 0; half < 2; ++half) {
            int e = m*16 + lg + half*8;
            float Ce = sC[e];
            if (Ce != 0.f) {
                int ii = si[e], jj = sj[e];
                const float* xr = g_xs + (size_t)jj * FDIM;
                float*       ar = g_agg + (size_t)ii * FDIM;
                #pragma unroll
                for (int t = 0; t < 4; ++t) {
                    int c0 = w*32 + t*8 + 2*lp;
                    float2 xv = *(const float2*)(xr + c0);
                    float d0 = (acc[m][t][half*2 + 0] + b2a[t]) * Ce * xv.x;
                    float d1 = (acc[m][t][half*2 + 1] + b2b[t]) * Ce * xv.y;
                    red_add_v2(&ar[c0], d0, d1);
                }
            }
        }
    }
}

// ---------------------------------------------------------------------------
// Node GEMM (scalar f32x2). mode 0: g_xs = in @ w.
// mode 1: out = xres + ssp(g_agg @ w + bias).
// ---------------------------------------------------------------------------
__device__ __forceinline__ u64 pack2(float lo, float hi) {
    u64 r; asm("mov.b64 %0, {%1, %2};" : "=l"(r) : "f"(lo), "f"(hi)); return r;
}
__device__ __forceinline__ void unpack2(u64 v, float& lo, float& hi) {
    asm("mov.b64 {%0, %1}, %2;" : "=f"(lo), "=f"(hi) : "l"(v));
}
__device__ __forceinline__ u64 ffma2(u64 a, u64 b, u64 c) {
    u64 d; asm("fma.rn.f32x2 %0, %1, %2, %3;" : "=l"(d) : "l"(a), "l"(b), "l"(c)); return d;
}

extern "C" __global__ void __launch_bounds__(256, 3)
node_gemm(const float* __restrict__ in,
          const float* __restrict__ w,
          const float* __restrict__ bias,
          const float* __restrict__ xres,
          float* __restrict__ out,
          int N, int mode)
{
    extern __shared__ float tile[];          // 32*256 floats
    const int tid = threadIdx.x;
    const int n0  = blockIdx.x * 32;

    const float* src = (mode == 0) ? in : (const float*)g_agg;
    float* dst       = (mode == 0) ? g_xs : out;

    {
        const float4* s4 = reinterpret_cast<const float4*>(src);
        float4* t4 = reinterpret_cast<float4*>(tile);
        #pragma unroll
        for (int q = 0; q < 8; ++q) {
            int idx = q * 256 + tid;
            int r = idx >> 6;
            float4 v = make_float4(0.f, 0.f, 0.f, 0.f);
            if (n0 + r < N) v = s4[(size_t)(n0 + r) * 64 + (idx & 63)];
            t4[idx] = v;
        }
    }
    __syncthreads();

    const int c = tid;
    #pragma unroll 1
    for (int ch = 0; ch < 2; ++ch) {
        u64 acc[16];
        #pragma unroll
        for (int r = 0; r < 16; ++r) acc[r] = 0ULL;

        float a0 = w[0*FDIM + c], a1 = w[1*FDIM + c];
        float a2 = w[2*FDIM + c], a3 = w[3*FDIM + c];
        float p0 = w[4*FDIM + c], p1 = w[5*FDIM + c];
        float p2 = w[6*FDIM + c], p3 = w[7*FDIM + c];
        #pragma unroll 1
        for (int kc = 0; kc < 64; ++kc) {
            u64 wp0 = pack2(a0, a1);
            u64 wp1 = pack2(a2, a3);
            a0 = p0; a1 = p1; a2 = p2; a3 = p3;
            if (kc + 2 < 64) {
                int k0 = (kc + 2) * 4;
                p0 = w[(k0+0)*FDIM + c]; p1 = w[(k0+1)*FDIM + c];
                p2 = w[(k0+2)*FDIM + c]; p3 = w[(k0+3)*FDIM + c];
            }
            const float* base = tile + (ch * 16) * FDIM + kc * 4;
            #pragma unroll
            for (int r = 0; r < 16; ++r) {
                ulonglong2 v = *reinterpret_cast<const ulonglong2*>(base + r*FDIM);
                acc[r] = ffma2(v.x, wp0, acc[r]);
                acc[r] = ffma2(v.y, wp1, acc[r]);
            }
        }
        #pragma unroll
        for (int r = 0; r < 16; ++r) {
            int n = n0 + ch * 16 + r;
            if (n < N) {
                float lo, hi; unpack2(acc[r], lo, hi);
                float val = lo + hi;
                if (mode == 0) dst[n * FDIM + c] = val;
                else dst[n * FDIM + c] = xres[n * FDIM + c] + sspf(val + bias[c]);
            }
        }
    }
}

// ---------------------------------------------------------------------------

static const int SMEM_NODE = 32 * FDIM * 4;

extern "C" void kernel_launch(void* const* d_in, const int* in_sizes, int n_in,
                              void* d_out, int out_size)
{
    const float* x    = (const float*)d_in[0];
    const void*  eidx = d_in[1];
    const float* ew   = (const float*)d_in[2];
    const float* ea   = (const float*)d_in[3];
    const float* w1   = (const float*)d_in[4];
    const float* b1   = (const float*)d_in[5];
    const float* w2   = (const float*)d_in[6];
    const float* b2   = (const float*)d_in[7];
    const float* l1   = (const float*)d_in[8];
    const float* l2   = (const float*)d_in[9];
    const float* l2b  = (const float*)d_in[10];

    const int N = in_sizes[0] / FDIM;     // x is [N,256]
    const int E = in_sizes[1] / 2;        // edge_index is [2,E]

    cudaFuncSetAttribute(edge_kernel, cudaFuncAttributeMaxDynamicSharedMemorySize, SMEM_EDGE);
    cudaFuncSetAttribute(node_gemm,   cudaFuncAttributeMaxDynamicSharedMemorySize, SMEM_NODE);

    int count64 = E / 2 < 32 ? E / 2 : 32;
    detect_idx_kernel<<<1, 32>>>((const long long*)eidx, count64, N);   // zeroes g_ecount
    cull_kernel<<<(E + 255) / 256, 256>>>(eidx, ew, E, N);

    const int total4 = (N * FDIM) / 4;
    zero_agg_kernel<<<(total4 + 255) / 256, 256>>>(total4);

    prep_w2t<<<256, 256>>>(w2);
    prep_w1t<<<64, 256>>>(w1);

    // xs = x @ lin1_w  -> g_xs
    node_gemm<<<(N + 31) / 32, 256, SMEM_NODE>>>(x, l1, nullptr, nullptr,
                                                 nullptr, N, 0);

    warm_kernel<<<64, 256>>>(16384);

    // fused edge MLP (both layers on mma.sync fp16) + scatter-add
    edge_kernel<<<(E + EDG - 1) / EDG, 256, SMEM_EDGE>>>(ea, b1, b2);

    // out = x + ssp(agg @ lin2_w + lin2_b)
    node_gemm<<<(N + 31) / 32, 256, SMEM_NODE>>>(nullptr, l2, l2b, x,
                                                 (float*)d_out, N, 1);
}

// round 17
// speedup vs baseline: 5.0701x; 1.5229x over previous
#include <cuda_runtime.h>
#include <cuda_fp16.h>
#include <cstdint>

// ---------------------------------------------------------------------------
// InteractionBlock (SchNet CFConv).  R17:
//  - single-term fp16 HMMA everywhere (error ledger shows ~30x damping of
//    2^-11 sources; measured 1.7e-5 with 2 sources -> ~4e-5 with 8).
//  - edge kernel: 62KB smem -> 3 CTAs/SM; mma/LDS halved vs R16.
//  - node GEMMs on the same mma skeleton (chunked l1t/l2t fp16 streams).
//  - edge culling (~26% C=0) + red.add.v2 epilogue retained.
// ---------------------------------------------------------------------------

#define FDIM 256
#define GDIM 50

#define NMAX 10240
#define EMAX 330000
__device__ __align__(16) float g_xs[NMAX * FDIM];
__device__ __align__(16) float g_agg[NMAX * FDIM];
__device__ int   g_si[EMAX];
__device__ int   g_sj[EMAX];
__device__ float g_C[EMAX];
__device__ int   g_eid[EMAX];
__device__ int   g_ecount;
__device__ int   g_idx64;
// transposed fp16 weights, chunked [kc][n 256][kk 32]
__device__ __align__(16) __half g_w2t[8 * 256 * 32];
__device__ __align__(16) __half g_w1t[2 * 256 * 32];   // k>=50 zero
__device__ __align__(16) __half g_l1t[8 * 256 * 32];
__device__ __align__(16) __half g_l2t[8 * 256 * 32];

__device__ __forceinline__ float sspf(float v) {
    float t = __expf(-fabsf(v));
    return fmaxf(v, 0.f) + __logf(1.f + t) - 0.69314718055994530942f;
}

// ---- base-ISA tensor core mma (fp16 in, fp32 accum) ------------------------
__device__ __forceinline__ void mma16816(float* d,
    uint32_t a0, uint32_t a1, uint32_t a2, uint32_t a3,
    uint32_t b0, uint32_t b1)
{
    asm volatile(
        "mma.sync.aligned.m16n8k16.row.col.f32.f16.f16.f32 "
        "{%0,%1,%2,%3}, {%4,%5,%6,%7}, {%8,%9}, {%0,%1,%2,%3};"
        : "+f"(d[0]), "+f"(d[1]), "+f"(d[2]), "+f"(d[3])
        : "r"(a0), "r"(a1), "r"(a2), "r"(a3), "r"(b0), "r"(b1));
}

// ---- cp.async / misc -------------------------------------------------------
__device__ __forceinline__ void cp16(uint32_t smem_dst, const void* gsrc) {
    asm volatile("cp.async.cg.shared.global [%0], [%1], 16;"
                 :: "r"(smem_dst), "l"(gsrc) : "memory");
}
__device__ __forceinline__ void cp_commit() {
    asm volatile("cp.async.commit_group;" ::: "memory");
}
template <int N> __device__ __forceinline__ void cp_wait() {
    asm volatile("cp.async.wait_group %0;" :: "n"(N) : "memory");
}
__device__ __forceinline__ uint32_t smem_u32(const void* p) {
    uint32_t a;
    asm("{ .reg .u64 t; cvta.to.shared.u64 t, %1; cvt.u32.u64 %0, t; }"
        : "=r"(a) : "l"(p));
    return a;
}
__device__ __forceinline__ void red_add_v2(float* ptr, float x, float y) {
    asm volatile("red.global.add.v2.f32 [%0], {%1, %2};"
                 :: "l"(ptr), "f"(x), "f"(y) : "memory");
}

// one chunk = 256 rows x 64 B fp16 (smem stride 80): 1024 cp16
#define B_STRB   80
#define BUF_SZ   20480
__device__ __forceinline__ void load_chunk(uint32_t dbase,
                                           const __half* gchunk, int tid)
{
    const char* src = (const char*)gchunk;
    #pragma unroll
    for (int q = 0; q < 4; ++q) {
        int t = q * 256 + tid;
        int row = t >> 2, seg = t & 3;
        cp16(dbase + row * B_STRB + seg * 16, src + row * 64 + seg * 16);
    }
}

// ---------------------------------------------------------------------------
extern "C" __global__ void detect_idx_kernel(const long long* __restrict__ p,
                                             int count64, int N)
{
    int lane = threadIdx.x;
    int ok = 1;
    if (lane < count64) {
        long long v = p[lane];
        ok = (v >= 0 && v < (long long)N) ? 1 : 0;
    }
    unsigned all = __ballot_sync(0xFFFFFFFFu, ok);
    if (lane == 0) { g_idx64 = (all == 0xFFFFFFFFu) ? 1 : 0; g_ecount = 0; }
}

extern "C" __global__ void cull_kernel(const void* __restrict__ p,
                                       const float* __restrict__ ew,
                                       int E, int N)
{
    int e = blockIdx.x * blockDim.x + threadIdx.x;
    if (e >= E) return;
    float a = ew[e*3+0], b = ew[e*3+1], c2 = ew[e*3+2];
    float d = sqrtf(a*a + b*b + c2*c2);
    if (d > 2.0f) return;
    float C = 0.5f * (__cosf(d * 1.57079632679489662f) + 1.f);
    int iv, jv;
    if (g_idx64) {
        const long long* q = (const long long*)p;
        iv = (int)q[e]; jv = (int)q[E + e];
    } else {
        const int* q = (const int*)p;
        iv = q[e]; jv = q[E + e];
    }
    int pos = atomicAdd(&g_ecount, 1);
    g_si[pos]  = min(max(iv, 0), N - 1);
    g_sj[pos]  = min(max(jv, 0), N - 1);
    g_C[pos]   = C;
    g_eid[pos] = e;
}

// fused weight prep: w2t(256 blk) | w1t(64) | l1t(256) | l2t(256)
extern "C" __global__ void prep_all(const float* __restrict__ w1,
                                    const float* __restrict__ w2,
                                    const float* __restrict__ l1,
                                    const float* __restrict__ l2)
{
    int b = blockIdx.x, t = threadIdx.x;
    if (b < 256) {
        int idx = b * 256 + t, k = idx >> 8, n = idx & 255;
        g_w2t[(k >> 5) * 8192 + n * 32 + (k & 31)] = __float2half_rn(w2[k * 256 + n]);
    } else if (b < 320) {
        int idx = (b - 256) * 256 + t, n = idx >> 6, k = idx & 63;
        g_w1t[(k >> 5) * 8192 + n * 32 + (k & 31)] =
            __float2half_rn(k < GDIM ? w1[k * FDIM + n] : 0.f);
    } else if (b < 576) {
        int idx = (b - 320) * 256 + t, k = idx >> 8, n = idx & 255;
        g_l1t[(k >> 5) * 8192 + n * 32 + (k & 31)] = __float2half_rn(l1[k * 256 + n]);
    } else {
        int idx = (b - 576) * 256 + t, k = idx >> 8, n = idx & 255;
        g_l2t[(k >> 5) * 8192 + n * 32 + (k & 31)] = __float2half_rn(l2[k * 256 + n]);
    }
}

extern "C" __global__ void zero_agg_kernel(int total4) {
    int i = blockIdx.x * blockDim.x + threadIdx.x;
    if (i < total4) {
        float4 z; z.x = 0.f; z.y = 0.f; z.z = 0.f; z.w = 0.f;
        reinterpret_cast<float4*>(g_agg)[i] = z;
    }
}

// ---------------------------------------------------------------------------
// Fused edge kernel: 32 compacted edges/CTA, 256 threads, 3 CTAs/SM.
// smem: HID [0,16896) 32x264 fp16 (stride 528)
//       BBUF [16896,57856) 2 x 20480 (chunk [256n][32k] stride 80)
//       EA   [57856,62976) 2 chunks x [32r][32k] stride 80
//       aux -> 63360
// ---------------------------------------------------------------------------
#define EDG      32
#define HID_STRB 528
#define HID_OFF  0
#define BBUF     16896
#define EA_OFF   57856
#define EA_CHK   2560
#define SC_OFF   62976
#define SI_OFF   63104
#define SJ_OFF   63232
#define SMEM_EDGE 63360

extern "C" __global__ void __launch_bounds__(256, 3)
edge_kernel(const float* __restrict__ ea,
            const float* __restrict__ b1,
            const float* __restrict__ b2)
{
    const int EC = g_ecount;
    const int e0 = blockIdx.x * EDG;
    if (e0 >= EC) return;

    extern __shared__ char smem_raw[];
    const uint32_t sbase = smem_u32(smem_raw);
    const int tid = threadIdx.x;

    float* sC = (float*)(smem_raw + SC_OFF);
    int*   si = (int*)(smem_raw + SI_OFF);
    int*   sj = (int*)(smem_raw + SJ_OFF);

    if (tid < EDG) {
        int e = e0 + tid;
        float C = 0.f; int iv = 0, jv = 0;
        if (e < EC) { iv = g_si[e]; jv = g_sj[e]; C = g_C[e]; }
        si[tid] = iv; sj[tid] = jv; sC[tid] = C;
    }

    // gather edge_attr into chunked EA slabs (fp16, zero-padded)
    #pragma unroll
    for (int q = 0; q < 8; ++q) {
        int idx = q * 256 + tid;            // [0, 2048)
        int r = idx >> 6, k = idx & 63;
        float v = 0.f;
        int e = e0 + r;
        if (k < GDIM && e < EC) v = ea[(size_t)g_eid[e] * GDIM + k];
        *(__half*)(smem_raw + EA_OFF + (k >> 5) * EA_CHK + r * B_STRB + (k & 31) * 2)
            = __float2half_rn(v);
    }

    // pipeline prologue: w1 chunks 0,1
    load_chunk(sbase + BBUF,          g_w1t,        tid); cp_commit();
    load_chunk(sbase + BBUF + BUF_SZ, g_w1t + 8192, tid); cp_commit();

    const int lane = tid & 31;
    const int w    = tid >> 5;          // warp owns cols [w*32, w*32+32)
    const int lp   = lane & 3;
    const int lg   = lane >> 2;

    // ---------------- Stage A: hid = ssp(ea@W1+b1) -------------------------
    {
        float accA[2][4][4];
        #pragma unroll
        for (int m = 0; m < 2; ++m)
            #pragma unroll
            for (int t = 0; t < 4; ++t)
                #pragma unroll
                for (int q = 0; q < 4; ++q) accA[m][t][q] = 0.f;

        #pragma unroll 1
        for (int kc = 0; kc < 2; ++kc) {
            cp_wait<1>();
            __syncthreads();

            const char* Bbase = smem_raw + BBUF + (kc & 1) * BUF_SZ;
            #pragma unroll
            for (int ks = 0; ks < 2; ++ks) {
                uint32_t bfr[4][2];
                #pragma unroll
                for (int t = 0; t < 4; ++t) {
                    const char* bp = Bbase + (w*32 + t*8 + lg) * B_STRB + ks*32 + lp*4;
                    bfr[t][0] = *(const uint32_t*)bp;
                    bfr[t][1] = *(const uint32_t*)(bp + 16);
                }
                #pragma unroll
                for (int m = 0; m < 2; ++m) {
                    const char* ap = smem_raw + EA_OFF + kc * EA_CHK
                                   + (m*16 + lg) * B_STRB + ks*32 + lp*4;
                    uint32_t a0 = *(const uint32_t*)ap;
                    uint32_t a1 = *(const uint32_t*)(ap + 8 * B_STRB);
                    uint32_t a2 = *(const uint32_t*)(ap + 16);
                    uint32_t a3 = *(const uint32_t*)(ap + 8 * B_STRB + 16);
                    #pragma unroll
                    for (int t = 0; t < 4; ++t)
                        mma16816(accA[m][t], a0, a1, a2, a3, bfr[t][0], bfr[t][1]);
                }
            }
            __syncthreads();
            load_chunk(sbase + BBUF + (kc & 1) * BUF_SZ, g_w2t + kc * 8192, tid);
            cp_commit();
        }

        // ssp + b1, store hid (fp16)
        float b1a[4], b1b[4];
        #pragma unroll
        for (int t = 0; t < 4; ++t) {
            int c0 = w*32 + t*8 + 2*lp;
            b1a[t] = b1[c0]; b1b[t] = b1[c0 + 1];
        }
        #pragma unroll
        for (int m = 0; m < 2; ++m) {
            #pragma unroll
            for (int half = 0; half < 2; ++half) {
                int row = m*16 + lg + half*8;
                #pragma unroll
                for (int t = 0; t < 4; ++t) {
                    int c0 = w*32 + t*8 + 2*lp;
                    __half h0 = __float2half_rn(sspf(accA[m][t][half*2 + 0] + b1a[t]));
                    __half h1 = __float2half_rn(sspf(accA[m][t][half*2 + 1] + b1b[t]));
                    uint32_t hp = ((uint32_t)__half_as_ushort(h1) << 16) | __half_as_ushort(h0);
                    *(uint32_t*)(smem_raw + HID_OFF + row * HID_STRB + c0 * 2) = hp;
                }
            }
        }
    }

    // ---------------- Stage B: W = hid @ w2 --------------------------------
    float acc[2][4][4];
    #pragma unroll
    for (int m = 0; m < 2; ++m)
        #pragma unroll
        for (int t = 0; t < 4; ++t)
            #pragma unroll
            for (int q = 0; q < 4; ++q) acc[m][t][q] = 0.f;

    #pragma unroll 1
    for (int kc = 0; kc < 8; ++kc) {
        if (kc == 7) cp_wait<0>(); else cp_wait<1>();
        __syncthreads();

        const char* Bbase = smem_raw + BBUF + (kc & 1) * BUF_SZ;
        #pragma unroll
        for (int ks = 0; ks < 2; ++ks) {
            uint32_t bfr[4][2];
            #pragma unroll
            for (int t = 0; t < 4; ++t) {
                const char* bp = Bbase + (w*32 + t*8 + lg) * B_STRB + ks*32 + lp*4;
                bfr[t][0] = *(const uint32_t*)bp;
                bfr[t][1] = *(const uint32_t*)(bp + 16);
            }
            #pragma unroll
            for (int m = 0; m < 2; ++m) {
                const char* ap = smem_raw + HID_OFF + (m*16 + lg) * HID_STRB
                               + kc*64 + ks*32 + lp*4;
                uint32_t a0 = *(const uint32_t*)ap;
                uint32_t a1 = *(const uint32_t*)(ap + 8 * HID_STRB);
                uint32_t a2 = *(const uint32_t*)(ap + 16);
                uint32_t a3 = *(const uint32_t*)(ap + 8 * HID_STRB + 16);
                #pragma unroll
                for (int t = 0; t < 4; ++t)
                    mma16816(acc[m][t], a0, a1, a2, a3, bfr[t][0], bfr[t][1]);
            }
        }
        __syncthreads();
        if (kc + 2 < 8) {
            load_chunk(sbase + BBUF + (kc & 1) * BUF_SZ, g_w2t + (kc + 2) * 8192, tid);
            cp_commit();
        }
    }

    // ---------------- epilogue: (D+b2)*C*xs[j] -> red.v2 agg[i] ------------
    float b2a[4], b2b[4];
    #pragma unroll
    for (int t = 0; t < 4; ++t) {
        int c0 = w*32 + t*8 + 2*lp;
        b2a[t] = b2[c0];
        b2b[t] = b2[c0 + 1];
    }
    #pragma unroll
    for (int m = 0; m < 2; ++m) {
        #pragma unroll
        for (int half = 0; half < 2; ++half) {
            int e = m*16 + lg + half*8;
            float Ce = sC[e];
            if (Ce != 0.f) {
                int ii = si[e], jj = sj[e];
                const float* xr = g_xs + (size_t)jj * FDIM;
                float*       ar = g_agg + (size_t)ii * FDIM;
                #pragma unroll
                for (int t = 0; t < 4; ++t) {
                    int c0 = w*32 + t*8 + 2*lp;
                    float2 xv = *(const float2*)(xr + c0);
                    float d0 = (acc[m][t][half*2 + 0] + b2a[t]) * Ce * xv.x;
                    float d1 = (acc[m][t][half*2 + 1] + b2b[t]) * Ce * xv.y;
                    red_add_v2(&ar[c0], d0, d1);
                }
            }
        }
    }
}

// ---------------------------------------------------------------------------
// Node GEMM on mma: 32 rows/CTA, 256 threads, 3 CTAs/SM.
// mode 0: g_xs = in @ l1.   mode 1: out = xres + ssp(g_agg @ l2 + bias).
// smem: NG_A [0,20480) 8 chunks x [32r][32k] stride 80; BBUF 2 x 20480.
// ---------------------------------------------------------------------------
#define NG_A     0
#define NG_BBUF  20480
#define SMEM_NODE (20480 + 2 * BUF_SZ)

extern "C" __global__ void __launch_bounds__(256, 3)
node_mma(const float* __restrict__ in,
         const float* __restrict__ bias,
         const float* __restrict__ xres,
         float* __restrict__ out,
         int N, int mode)
{
    extern __shared__ char smem_raw[];
    const uint32_t sbase = smem_u32(smem_raw);
    const int tid = threadIdx.x;
    const int n0  = blockIdx.x * 32;

    const float* src = mode ? (const float*)g_agg : in;
    const __half* bt = mode ? g_l2t : g_l1t;

    // A tile: 32 rows x 256 k fp32 -> fp16 chunked [kc8][32r][32k] stride 80
    {
        const float4* s4 = reinterpret_cast<const float4*>(src);
        #pragma unroll
        for (int q = 0; q < 8; ++q) {
            int idx = q * 256 + tid;           // [0,2048) float4s
            int r = idx >> 6, seg = idx & 63;
            float4 v = make_float4(0.f, 0.f, 0.f, 0.f);
            if (n0 + r < N) v = s4[(size_t)(n0 + r) * 64 + seg];
            int k = seg * 4;
            __half2 p0 = __floats2half2_rn(v.x, v.y);
            __half2 p1 = __floats2half2_rn(v.z, v.w);
            uint32_t u0, u1;
            u0 = *(uint32_t*)&p0; u1 = *(uint32_t*)&p1;
            uint2 st; st.x = u0; st.y = u1;
            *(uint2*)(smem_raw + NG_A + (k >> 5) * 2560 + r * B_STRB + (k & 31) * 2) = st;
        }
    }

    load_chunk(sbase + NG_BBUF,          bt,        tid); cp_commit();
    load_chunk(sbase + NG_BBUF + BUF_SZ, bt + 8192, tid); cp_commit();

    const int lane = tid & 31;
    const int w    = tid >> 5;
    const int lp   = lane & 3;
    const int lg   = lane >> 2;

    float acc[2][4][4];
    #pragma unroll
    for (int m = 0; m < 2; ++m)
        #pragma unroll
        for (int t = 0; t < 4; ++t)
            #pragma unroll
            for (int q = 0; q < 4; ++q) acc[m][t][q] = 0.f;

    #pragma unroll 1
    for (int kc = 0; kc < 8; ++kc) {
        if (kc == 7) cp_wait<0>(); else cp_wait<1>();
        __syncthreads();

        const char* Bbase = smem_raw + NG_BBUF + (kc & 1) * BUF_SZ;
        #pragma unroll
        for (int ks = 0; ks < 2; ++ks) {
            uint32_t bfr[4][2];
            #pragma unroll
            for (int t = 0; t < 4; ++t) {
                const char* bp = Bbase + (w*32 + t*8 + lg) * B_STRB + ks*32 + lp*4;
                bfr[t][0] = *(const uint32_t*)bp;
                bfr[t][1] = *(const uint32_t*)(bp + 16);
            }
            #pragma unroll
            for (int m = 0; m < 2; ++m) {
                const char* ap = smem_raw + NG_A + kc * 2560
                               + (m*16 + lg) * B_STRB + ks*32 + lp*4;
                uint32_t a0 = *(const uint32_t*)ap;
                uint32_t a1 = *(const uint32_t*)(ap + 8 * B_STRB);
                uint32_t a2 = *(const uint32_t*)(ap + 16);
                uint32_t a3 = *(const uint32_t*)(ap + 8 * B_STRB + 16);
                #pragma unroll
                for (int t = 0; t < 4; ++t)
                    mma16816(acc[m][t], a0, a1, a2, a3, bfr[t][0], bfr[t][1]);
            }
        }
        __syncthreads();
        if (kc + 2 < 8) {
            load_chunk(sbase + NG_BBUF + (kc & 1) * BUF_SZ, bt + (kc + 2) * 8192, tid);
            cp_commit();
        }
    }

    // epilogue
    float ba[4], bb[4];
    if (mode) {
        #pragma unroll
        for (int t = 0; t < 4; ++t) {
            int c0 = w*32 + t*8 + 2*lp;
            ba[t] = bias[c0]; bb[t] = bias[c0 + 1];
        }
    }
    #pragma unroll
    for (int m = 0; m < 2; ++m) {
        #pragma unroll
        for (int half = 0; half < 2; ++half) {
            int row = n0 + m*16 + lg + half*8;
            if (row < N) {
                #pragma unroll
                for (int t = 0; t < 4; ++t) {
                    int c0 = w*32 + t*8 + 2*lp;
                    float d0 = acc[m][t][half*2 + 0];
                    float d1 = acc[m][t][half*2 + 1];
                    float2 o;
                    if (mode) {
                        float2 xv = *(const float2*)(xres + (size_t)row * FDIM + c0);
                        o.x = xv.x + sspf(d0 + ba[t]);
                        o.y = xv.y + sspf(d1 + bb[t]);
                        *(float2*)(out + (size_t)row * FDIM + c0) = o;
                    } else {
                        o.x = d0; o.y = d1;
                        *(float2*)(g_xs + (size_t)row * FDIM + c0) = o;
                    }
                }
            }
        }
    }
}

// ---------------------------------------------------------------------------

extern "C" void kernel_launch(void* const* d_in, const int* in_sizes, int n_in,
                              void* d_out, int out_size)
{
    const float* x    = (const float*)d_in[0];
    const void*  eidx = d_in[1];
    const float* ew   = (const float*)d_in[2];
    const float* ea   = (const float*)d_in[3];
    const float* w1   = (const float*)d_in[4];
    const float* b1   = (const float*)d_in[5];
    const float* w2   = (const float*)d_in[6];
    const float* b2   = (const float*)d_in[7];
    const float* l1   = (const float*)d_in[8];
    const float* l2   = (const float*)d_in[9];
    const float* l2b  = (const float*)d_in[10];

    const int N = in_sizes[0] / FDIM;     // x is [N,256]
    const int E = in_sizes[1] / 2;        // edge_index is [2,E]

    cudaFuncSetAttribute(edge_kernel, cudaFuncAttributeMaxDynamicSharedMemorySize, SMEM_EDGE);
    cudaFuncSetAttribute(node_mma,    cudaFuncAttributeMaxDynamicSharedMemorySize, SMEM_NODE);

    int count64 = E / 2 < 32 ? E / 2 : 32;
    detect_idx_kernel<<<1, 32>>>((const long long*)eidx, count64, N);   // 0
    cull_kernel<<<(E + 255) / 256, 256>>>(eidx, ew, E, N);              // 1

    const int total4 = (N * FDIM) / 4;
    zero_agg_kernel<<<(total4 + 255) / 256, 256>>>(total4);             // 2

    prep_all<<<832, 256>>>(w1, w2, l1, l2);                             // 3

    // xs = x @ lin1_w -> g_xs
    node_mma<<<(N + 31) / 32, 256, SMEM_NODE>>>(x, nullptr, nullptr,    // 4
                                                nullptr, N, 0);

    // fused edge MLP (fp16 mma both layers) + scatter-add
    edge_kernel<<<(E + EDG - 1) / EDG, 256, SMEM_EDGE>>>(ea, b1, b2);   // 5 (ncu)

    // out = x + ssp(agg @ lin2_w + lin2_b)
    node_mma<<<(N + 31) / 32, 256, SMEM_NODE>>>(nullptr, l2b, x,        // 6
                                                (float*)d_out, N, 1);
}